// round 1
// baseline (speedup 1.0000x reference)
#include <cuda_runtime.h>

#define HH 64
#define WW 64
#define CIN 256
#define OC1 128

// Scratch (device globals: allocation-free, graph-capturable)
__device__ float g_k1[4 * OC1 * HH * WW];     // conv1 output [B][128][64][64]
__device__ float g_attn[4 * 49 * HH * WW];    // softmax attention [B][49][64][64]

// ---------------------------------------------------------------------------
// Kernel 1: dilated 7x7 conv, 256 -> 128, dilation 2, padding 6, + bias
// Block: 128 threads. Tile: 16x16 spatial x 32 output channels, one batch.
// Thread: 8 pixels (consecutive w) x 8 output channels register tile.
// ---------------------------------------------------------------------------
__global__ __launch_bounds__(128) void conv1_kernel(
    const float* __restrict__ x,
    const float* __restrict__ w1,
    const float* __restrict__ b1)
{
    const int tile = blockIdx.x;          // 0..15 : 4x4 spatial tiles
    const int ty = tile >> 2, tx = tile & 3;
    const int h0 = ty * 16, w0 = tx * 16;
    const int oc0 = blockIdx.y * 32;      // 0..3 oc tiles
    const int b = blockIdx.z;             // 0..3
    const int tid = threadIdx.x;

    const int ocg = tid >> 5;             // 0..3 -> 8 ocs each
    const int slot = tid & 31;
    const int row = slot >> 1;            // 0..15 output row in tile
    const int wl = (slot & 1) * 8;        // 0 or 8: 8 consecutive output cols

    __shared__ __align__(16) float xs[28 * 30];   // input tile, row stride 30
    __shared__ __align__(16) float ws[49 * 32];   // weights [tap][oc_local]

    float acc[8][8];
#pragma unroll
    for (int p = 0; p < 8; p++)
#pragma unroll
        for (int j = 0; j < 8; j++) acc[p][j] = 0.f;

#pragma unroll 1
    for (int ic = 0; ic < CIN; ic++) {
        __syncthreads();
        // load 28x28 input tile (zero-padded at borders)
        for (int idx = tid; idx < 28 * 28; idx += 128) {
            int r = idx / 28, c = idx - r * 28;
            int gh = h0 - 6 + r, gw = w0 - 6 + c;
            float v = 0.f;
            if (gh >= 0 && gh < HH && gw >= 0 && gw < WW)
                v = x[((b * CIN + ic) * HH + gh) * WW + gw];
            xs[r * 30 + c] = v;
        }
        // load 32 oc x 49 taps, store [tap][oc]
        for (int idx = tid; idx < 32 * 49; idx += 128) {
            int ocl = idx / 49, tap = idx - ocl * 49;
            ws[tap * 32 + ocl] = w1[(oc0 + ocl) * (CIN * 49) + ic * 49 + tap];
        }
        __syncthreads();

#pragma unroll 1
        for (int u = 0; u < 7; u++) {
            const float* xrow = &xs[(row + 2 * u) * 30];
#pragma unroll
            for (int v = 0; v < 7; v++) {
                const float* abase = xrow + wl + 2 * v;   // even offset -> 8B aligned
                float2 a01 = *(const float2*)(abase + 0);
                float2 a23 = *(const float2*)(abase + 2);
                float2 a45 = *(const float2*)(abase + 4);
                float2 a67 = *(const float2*)(abase + 6);
                float a[8] = {a01.x, a01.y, a23.x, a23.y, a45.x, a45.y, a67.x, a67.y};

                const float4* wsrc = (const float4*)(ws + (u * 7 + v) * 32 + ocg * 8);
                float4 bw0 = wsrc[0];
                float4 bw1 = wsrc[1];
                float bw[8] = {bw0.x, bw0.y, bw0.z, bw0.w, bw1.x, bw1.y, bw1.z, bw1.w};
#pragma unroll
                for (int p = 0; p < 8; p++)
#pragma unroll
                    for (int j = 0; j < 8; j++)
                        acc[p][j] = fmaf(a[p], bw[j], acc[p][j]);
            }
        }
    }

    // epilogue: + bias, store to g_k1
#pragma unroll
    for (int j = 0; j < 8; j++) {
        int oc = oc0 + ocg * 8 + j;
        float bias = b1[oc];
        float* dst = &g_k1[((b * OC1 + oc) * HH + (h0 + row)) * WW + (w0 + wl)];
        float4 v0 = make_float4(acc[0][j] + bias, acc[1][j] + bias,
                                acc[2][j] + bias, acc[3][j] + bias);
        float4 v1 = make_float4(acc[4][j] + bias, acc[5][j] + bias,
                                acc[6][j] + bias, acc[7][j] + bias);
        *(float4*)(dst + 0) = v0;
        *(float4*)(dst + 4) = v1;
    }
}

// ---------------------------------------------------------------------------
// Kernel 2: 1x1 conv 128 -> 49 + bias, then softmax over the 49 channels.
// One thread per pixel; w2 staged in smem (broadcast reads).
// ---------------------------------------------------------------------------
__global__ __launch_bounds__(256) void conv2_softmax_kernel(
    const float* __restrict__ w2,
    const float* __restrict__ b2)
{
    __shared__ float w2s[49 * 128];
    const int b = blockIdx.y;
    const int px = blockIdx.x * 256 + threadIdx.x;   // 0..4095

    for (int i = threadIdx.x; i < 49 * 128; i += 256) w2s[i] = w2[i];
    __syncthreads();

    float acc[49];
#pragma unroll
    for (int k = 0; k < 49; k++) acc[k] = b2[k];

    const float* k1p = g_k1 + (b * OC1) * (HH * WW) + px;
#pragma unroll 1
    for (int c = 0; c < 128; c++) {
        float v = k1p[c * (HH * WW)];
#pragma unroll
        for (int k = 0; k < 49; k++)
            acc[k] = fmaf(v, w2s[k * 128 + c], acc[k]);
    }

    float m = acc[0];
#pragma unroll
    for (int k = 1; k < 49; k++) m = fmaxf(m, acc[k]);
    float s = 0.f;
#pragma unroll
    for (int k = 0; k < 49; k++) { acc[k] = __expf(acc[k] - m); s += acc[k]; }
    float inv = 1.f / s;
#pragma unroll
    for (int k = 0; k < 49; k++)
        g_attn[(b * 49 + k) * (HH * WW) + px] = acc[k] * inv;
}

// ---------------------------------------------------------------------------
// Kernel 3: out[b,c,h,w] = sum_k attn[b,k,h,w] * x[b,c,h+2u-6,w+2v-6]
// attn held in registers per pixel-thread (reused across 64 channels/block).
// ---------------------------------------------------------------------------
__global__ __launch_bounds__(128) void gather_kernel(
    const float* __restrict__ x,
    float* __restrict__ out)
{
    const int tile = blockIdx.x;             // 0..31 : 8 h-tiles x 4 w-tiles
    const int ty = tile >> 2, tx = tile & 3;
    const int h0 = ty * 8, w0 = tx * 16;
    const int c0 = blockIdx.y * 64;          // 0..3 channel groups
    const int b = blockIdx.z;
    const int tid = threadIdx.x;             // 128 = 8 rows x 16 cols
    const int rr = tid >> 4, cc = tid & 15;
    const int h = h0 + rr, w = w0 + cc;

    float attn[49];
#pragma unroll
    for (int k = 0; k < 49; k++)
        attn[k] = g_attn[((b * 49 + k) * HH + h) * WW + w];

    __shared__ float xs[20 * 29];            // 8+12 rows, 16+12 cols (pad 29)

#pragma unroll 1
    for (int c = 0; c < 64; c++) {
        __syncthreads();
        for (int idx = tid; idx < 20 * 28; idx += 128) {
            int r = idx / 28, col = idx - r * 28;
            int gh = h0 - 6 + r, gw = w0 - 6 + col;
            float v = 0.f;
            if (gh >= 0 && gh < HH && gw >= 0 && gw < WW)
                v = x[((b * CIN + c0 + c) * HH + gh) * WW + gw];
            xs[r * 29 + col] = v;
        }
        __syncthreads();

        float o = 0.f;
#pragma unroll
        for (int u = 0; u < 7; u++)
#pragma unroll
            for (int v = 0; v < 7; v++)
                o = fmaf(attn[u * 7 + v], xs[(rr + 2 * u) * 29 + (cc + 2 * v)], o);

        out[((b * CIN + c0 + c) * HH + h) * WW + w] = o;
    }
}

// ---------------------------------------------------------------------------
extern "C" void kernel_launch(void* const* d_in, const int* in_sizes, int n_in,
                              void* d_out, int out_size)
{
    const float* x  = (const float*)d_in[0];   // [4,256,64,64]
    const float* w1 = (const float*)d_in[1];   // [128,256,7,7]
    const float* b1 = (const float*)d_in[2];   // [128]
    const float* w2 = (const float*)d_in[3];   // [49,128,1,1]
    const float* b2 = (const float*)d_in[4];   // [49]
    float* out = (float*)d_out;                // [4,256,64,64]

    conv1_kernel<<<dim3(16, 4, 4), 128>>>(x, w1, b1);
    conv2_softmax_kernel<<<dim3(16, 4), 256>>>(w2, b2);
    gather_kernel<<<dim3(32, 4, 4), 128>>>(x, out);
}

// round 2
// speedup vs baseline: 2.7425x; 2.7425x over previous
#include <cuda_runtime.h>

#define HH 64
#define WW 64
#define CIN 256
#define XP 76            // padded 64 + 2*6
#define NT 49            // 7x7 taps
#define OC2 49           // fused output channels
#define WSTRIDE 2404     // per-ic fused-weight stride (floats, 16B multiple)

// Scratch (device globals: allocation-free, graph-capturable)
__device__ float g_xpad[4 * CIN * XP * XP];        // padded input
__device__ float g_w12[CIN * WSTRIDE];             // fused weights [ic][tap*49+oc]
__device__ float g_b12[OC2];                       // fused bias
__device__ float g_k2[4 * 4 * OC2 * HH * WW];      // partial logits [icq][b][oc][px]
__device__ float g_attn[4 * OC2 * HH * WW];        // softmax attention

// ---- cp.async helpers -------------------------------------------------------
__device__ __forceinline__ void cp_async16(void* d, const void* s) {
    unsigned sm = (unsigned)__cvta_generic_to_shared(d);
    asm volatile("cp.async.ca.shared.global [%0], [%1], 16;" :: "r"(sm), "l"(s));
}
__device__ __forceinline__ void cp_async8(void* d, const void* s) {
    unsigned sm = (unsigned)__cvta_generic_to_shared(d);
    asm volatile("cp.async.ca.shared.global [%0], [%1], 8;" :: "r"(sm), "l"(s));
}
__device__ __forceinline__ void cp_commit() { asm volatile("cp.async.commit_group;"); }
__device__ __forceinline__ void cp_wait0()  { asm volatile("cp.async.wait_group 0;"); }

// ---------------------------------------------------------------------------
// Zero-pad x into g_xpad [b][c][76][76]
// ---------------------------------------------------------------------------
__global__ __launch_bounds__(256) void pad_x(const float* __restrict__ x) {
    const int c = blockIdx.x, b = blockIdx.y;
    float* dst = g_xpad + ((size_t)(b * CIN + c)) * XP * XP;
    const float* src = x + ((size_t)(b * CIN + c)) * HH * WW;
    for (int idx = threadIdx.x; idx < XP * XP; idx += 256) {
        int r = idx / XP, cc = idx - r * XP;
        float v = 0.f;
        if (r >= 6 && r < 70 && cc >= 6 && cc < 70)
            v = src[(r - 6) * WW + (cc - 6)];
        dst[idx] = v;
    }
}

// ---------------------------------------------------------------------------
// Fuse conv1+conv2 weights: W12[ic][tap][oc2] = sum_m w2[oc2][m]*w1[m][ic][tap]
// One block per ic.
// ---------------------------------------------------------------------------
__global__ __launch_bounds__(256) void fuse_w(const float* __restrict__ w1,
                                              const float* __restrict__ w2) {
    const int ic = blockIdx.x;
    const int tid = threadIdx.x;
    __shared__ float w2s[OC2 * 128];
    for (int i = tid; i < OC2 * 128; i += 256) w2s[i] = w2[i];
    __syncthreads();

    if (tid < 245) {
        const int tap = tid % 49, ocg = tid / 49;     // ocg 0..4 -> 10 ocs each
        float acc[10];
#pragma unroll
        for (int j = 0; j < 10; j++) acc[j] = 0.f;
        const float* w1p = w1 + ic * 49 + tap;        // stride 12544 over m
#pragma unroll 4
        for (int m = 0; m < 128; m++) {
            float a = __ldg(w1p + m * (CIN * 49));
#pragma unroll
            for (int j = 0; j < 10; j++) {
                int oc = ocg * 10 + j;
                if (oc < OC2) acc[j] = fmaf(a, w2s[oc * 128 + m], acc[j]);
            }
        }
#pragma unroll
        for (int j = 0; j < 10; j++) {
            int oc = ocg * 10 + j;
            if (oc < OC2) g_w12[ic * WSTRIDE + tap * 49 + oc] = acc[j];
        }
    }
    if (tid >= 245 && tid < 248)                      // zero the 3 pad floats
        g_w12[ic * WSTRIDE + 2401 + (tid - 245)] = 0.f;
}

__global__ void bias_fuse(const float* __restrict__ w2,
                          const float* __restrict__ b1,
                          const float* __restrict__ b2) {
    int oc = threadIdx.x;
    if (oc < OC2) {
        float s = b2[oc];
        for (int m = 0; m < 128; m++) s = fmaf(w2[oc * 128 + m], b1[m], s);
        g_b12[oc] = s;
    }
}

// ---------------------------------------------------------------------------
// Fused dilated conv: 256 -> 49, 7x7, dilation 2, pad 6 (no bias; bias in softmax)
// Block: 256 threads; 16x16 px tile, 56 oc slots (49 real), 64-ic slice.
// Thread: 8 rows x 1 col x 7 oc. Lane map gives conflict-free LDS.
// grid = (16 spatial, 4 icq, 4 b)
// ---------------------------------------------------------------------------
__global__ __launch_bounds__(256) void conv_fused() {
    const int tile = blockIdx.x, icq = blockIdx.y, b = blockIdx.z;
    const int h0 = (tile >> 2) * 16, w0 = (tile & 3) * 16;
    const int tid = threadIdx.x;
    const int ocg = tid >> 5;                 // 0..7 (7 used)
    const int pxg = tid & 31;
    const int col = pxg & 15, rowg = pxg >> 4;
    const int wo = (ocg < 7) ? ocg * 7 : 0;   // keep idle group in-bounds

    __shared__ __align__(16) float xs[2][28 * 30];
    __shared__ __align__(16) float ws[2][2432];

    const int ic0 = icq * 64;
    const float* xb0 = g_xpad + (((size_t)(b * CIN + ic0)) * XP + h0) * XP + w0;

    float acc[8][7];
#pragma unroll
    for (int q = 0; q < 8; q++)
#pragma unroll
        for (int j = 0; j < 7; j++) acc[q][j] = 0.f;

    // --- prologue loads for ic_local = 0 ---
    {
        const float* xsrc = xb0;
        for (int i = tid; i < 392; i += 256) {
            int r = i / 14, c = (i - r * 14) * 2;
            cp_async8(&xs[0][r * 30 + c], xsrc + r * XP + c);
        }
        const float* wsrc = g_w12 + (size_t)ic0 * WSTRIDE;
        for (int i = tid; i < 601; i += 256)
            cp_async16(&ws[0][i * 4], wsrc + i * 4);
        cp_commit();
    }

#pragma unroll 1
    for (int il = 0; il < 64; il++) {
        cp_wait0();
        __syncthreads();
        if (il < 63) {
            const int icn = ic0 + il + 1;
            const int bn = (il + 1) & 1;
            const float* xsrc = xb0 + (size_t)(il + 1) * XP * XP;
            for (int i = tid; i < 392; i += 256) {
                int r = i / 14, c = (i - r * 14) * 2;
                cp_async8(&xs[bn][r * 30 + c], xsrc + r * XP + c);
            }
            const float* wsrc = g_w12 + (size_t)icn * WSTRIDE;
            for (int i = tid; i < 601; i += 256)
                cp_async16(&ws[bn][i * 4], wsrc + i * 4);
            cp_commit();
        }
        const int bu = il & 1;
        const float* xbs = &xs[bu][rowg * 8 * 30 + col];
        const float* wbs = &ws[bu][wo];
#pragma unroll 1
        for (int u = 0; u < 7; u++) {
            const float* xr = xbs + 2 * u * 30;
            const float* wr = wbs + u * 7 * 49;
#pragma unroll
            for (int v = 0; v < 7; v++) {
                float a[8];
#pragma unroll
                for (int q = 0; q < 8; q++) a[q] = xr[q * 30 + 2 * v];
                float wv[7];
#pragma unroll
                for (int j = 0; j < 7; j++) wv[j] = wr[v * 49 + j];
#pragma unroll
                for (int q = 0; q < 8; q++)
#pragma unroll
                    for (int j = 0; j < 7; j++)
                        acc[q][j] = fmaf(a[q], wv[j], acc[q][j]);
            }
        }
    }

    // epilogue: store partial logits
    if (ocg < 7) {
#pragma unroll
        for (int j = 0; j < 7; j++) {
            int oc = ocg * 7 + j;
            float* dst = g_k2 + (((size_t)(icq * 4 + b) * OC2 + oc) * HH +
                                 (h0 + rowg * 8)) * WW + (w0 + col);
#pragma unroll
            for (int q = 0; q < 8; q++)
                dst[q * WW] = acc[q][j];
        }
    }
}

// ---------------------------------------------------------------------------
// Sum 4 ic-partials + fused bias, softmax over 49 channels -> g_attn
// ---------------------------------------------------------------------------
__global__ __launch_bounds__(128) void softmax_k() {
    const int b = blockIdx.y;
    const int px = blockIdx.x * 128 + threadIdx.x;
    __shared__ float bs[OC2];
    if (threadIdx.x < OC2) bs[threadIdx.x] = g_b12[threadIdx.x];
    __syncthreads();

    float v[OC2];
#pragma unroll
    for (int k = 0; k < OC2; k++) v[k] = bs[k];
#pragma unroll
    for (int icq = 0; icq < 4; icq++) {
        const float* p = g_k2 + ((size_t)(icq * 4 + b) * OC2) * (HH * WW) + px;
#pragma unroll
        for (int k = 0; k < OC2; k++) v[k] += p[k * (HH * WW)];
    }
    float m = v[0];
#pragma unroll
    for (int k = 1; k < OC2; k++) m = fmaxf(m, v[k]);
    float s = 0.f;
#pragma unroll
    for (int k = 0; k < OC2; k++) { v[k] = __expf(v[k] - m); s += v[k]; }
    float inv = 1.f / s;
#pragma unroll
    for (int k = 0; k < OC2; k++)
        g_attn[((size_t)(b * OC2 + k)) * (HH * WW) + px] = v[k] * inv;
}

// ---------------------------------------------------------------------------
// Gather: out[b,c,h,w] = sum_k attn[b,k,h,w] * xpad[b,c,h+2u,w+2v]
// ---------------------------------------------------------------------------
__global__ __launch_bounds__(128) void gather_kernel(float* __restrict__ out) {
    const int tile = blockIdx.x;               // 8 h-tiles x 4 w-tiles
    const int ty = tile >> 2, tx = tile & 3;
    const int h0 = ty * 8, w0 = tx * 16;
    const int c0 = blockIdx.y * 64;
    const int b = blockIdx.z;
    const int tid = threadIdx.x;               // 8 rows x 16 cols
    const int rr = tid >> 4, cc = tid & 15;
    const int h = h0 + rr, w = w0 + cc;

    float attn[NT];
#pragma unroll
    for (int k = 0; k < NT; k++)
        attn[k] = g_attn[(((size_t)(b * OC2 + k)) * HH + h) * WW + w];

    __shared__ float xsm[20 * 29];

#pragma unroll 1
    for (int c = 0; c < 64; c++) {
        __syncthreads();
        const float* src = g_xpad + (((size_t)(b * CIN + c0 + c)) * XP + h0) * XP + w0;
        for (int idx = tid; idx < 20 * 28; idx += 128) {
            int r = idx / 28, col2 = idx - r * 28;
            xsm[r * 29 + col2] = src[r * XP + col2];
        }
        __syncthreads();

        float o = 0.f;
#pragma unroll
        for (int u = 0; u < 7; u++)
#pragma unroll
            for (int v = 0; v < 7; v++)
                o = fmaf(attn[u * 7 + v], xsm[(rr + 2 * u) * 29 + (cc + 2 * v)], o);

        out[(((size_t)(b * CIN + c0 + c)) * HH + h) * WW + w] = o;
    }
}

// ---------------------------------------------------------------------------
extern "C" void kernel_launch(void* const* d_in, const int* in_sizes, int n_in,
                              void* d_out, int out_size)
{
    const float* x  = (const float*)d_in[0];   // [4,256,64,64]
    const float* w1 = (const float*)d_in[1];   // [128,256,7,7]
    const float* b1 = (const float*)d_in[2];   // [128]
    const float* w2 = (const float*)d_in[3];   // [49,128,1,1]
    const float* b2 = (const float*)d_in[4];   // [49]
    float* out = (float*)d_out;                // [4,256,64,64]

    pad_x<<<dim3(CIN, 4), 256>>>(x);
    fuse_w<<<CIN, 256>>>(w1, w2);
    bias_fuse<<<1, 64>>>(w2, b1, b2);
    conv_fused<<<dim3(16, 4, 4), 256>>>();
    softmax_k<<<dim3(32, 4), 128>>>();
    gather_kernel<<<dim3(32, 4, 4), 128>>>(out);
}

// round 4
// speedup vs baseline: 3.9936x; 1.4562x over previous
#include <cuda_runtime.h>
#include <cstdint>

#define HH 64
#define WW 64
#define CIN 256
#define XP 76
#define OC2 49
#define KTOT 12544            // 49 taps * 256 ic
#define NQ 196                // K chunks of 64
#define ASTRIDE 72            // smem row stride (floats): conflict-free + 16B aligned
#define STG_A (128 * ASTRIDE * 4)
#define STG_B (64 * ASTRIDE * 4)
#define STAGE (STG_A + STG_B)
#define SMEM_CONV (3 * STAGE)
#define GSTRIDE 36

// Scratch (device globals: allocation-free, graph-capturable)
__device__ float g_xpad[4 * CIN * XP * XP];      // NCHW padded fp32 (gather)
__device__ float g_xn[4 * XP * XP * CIN];        // NHWC padded tf32-rounded (conv A)
__device__ float g_w12t[64 * KTOT];              // fused W^T [oc64][k], tf32-rounded
__device__ float g_b12[OC2];                     // fused bias (fp32)
__device__ float g_attn[4 * OC2 * HH * WW];      // softmax attention

// ---------------- helpers ----------------
__device__ __forceinline__ uint32_t smem_u32(const void* p) {
    uint32_t a;
    asm("{ .reg .u64 t; cvta.to.shared.u64 t, %1; cvt.u32.u64 %0, t; }" : "=r"(a) : "l"(p));
    return a;
}
__device__ __forceinline__ float to_tf32(float x) {
    uint32_t u;
    asm("cvt.rna.tf32.f32 %0, %1;" : "=r"(u) : "f"(x));
    return __uint_as_float(u);
}
__device__ __forceinline__ void cp16(uint32_t d, const void* s) {
    asm volatile("cp.async.cg.shared.global [%0], [%1], 16;" :: "r"(d), "l"(s));
}
#define CP_COMMIT() asm volatile("cp.async.commit_group;")
#define CP_WAIT(n)  asm volatile("cp.async.wait_group %0;" :: "n"(n))

__device__ __forceinline__ void mma_tf32(float* c, uint32_t a0, uint32_t a1,
                                         uint32_t a2, uint32_t a3,
                                         uint32_t b0, uint32_t b1) {
    asm volatile(
        "mma.sync.aligned.m16n8k8.row.col.f32.tf32.tf32.f32 "
        "{%0,%1,%2,%3},{%4,%5,%6,%7},{%8,%9},{%0,%1,%2,%3};"
        : "+f"(c[0]), "+f"(c[1]), "+f"(c[2]), "+f"(c[3])
        : "r"(a0), "r"(a1), "r"(a2), "r"(a3), "r"(b0), "r"(b1));
}

// ---------------------------------------------------------------------------
// NCHW zero-padded copy (fp32, for gather)
// ---------------------------------------------------------------------------
__global__ __launch_bounds__(256) void pad_x(const float* __restrict__ x) {
    const int c = blockIdx.x, b = blockIdx.y;
    float* dst = g_xpad + ((size_t)(b * CIN + c)) * XP * XP;
    const float* src = x + ((size_t)(b * CIN + c)) * HH * WW;
    for (int idx = threadIdx.x; idx < XP * XP; idx += 256) {
        int r = idx / XP, cc = idx - r * XP;
        float v = 0.f;
        if (r >= 6 && r < 70 && cc >= 6 && cc < 70)
            v = src[(r - 6) * WW + (cc - 6)];
        dst[idx] = v;
    }
}

// ---------------------------------------------------------------------------
// NHWC zero-padded transpose with tf32 rounding: g_xn[b][r][c][ic]
// ---------------------------------------------------------------------------
__global__ __launch_bounds__(256) void nhwc_pad(const float* __restrict__ x) {
    const int r = blockIdx.x, b = blockIdx.y;
    float* outr = g_xn + (((size_t)b * XP + r)) * XP * CIN;
    if (r < 6 || r >= 70) {
        for (int i = threadIdx.x; i < XP * CIN; i += 256) outr[i] = 0.f;
        return;
    }
    const int h = r - 6;
    __shared__ float sm[128 * 65];
    for (int half = 0; half < 2; half++) {
        const int ich = half * 128;
        for (int idx = threadIdx.x; idx < 128 * 64; idx += 256) {
            int icl = idx >> 6, w = idx & 63;
            sm[icl * 65 + w] = x[(((size_t)(b * CIN + ich + icl)) * HH + h) * WW + w];
        }
        __syncthreads();
        for (int idx = threadIdx.x; idx < 64 * 128; idx += 256) {
            int w = idx >> 7, icl = idx & 127;
            outr[(size_t)(w + 6) * CIN + ich + icl] = to_tf32(sm[icl * 65 + w]);
        }
        __syncthreads();
    }
    for (int idx = threadIdx.x; idx < 12 * CIN; idx += 256) {
        int cb = idx >> 8, ic = idx & 255;
        int c = (cb < 6) ? cb : cb + 64;
        outr[(size_t)c * CIN + ic] = 0.f;
    }
}

// ---------------------------------------------------------------------------
// Fused weights: g_w12t[oc][tap*256+ic] = sum_m w2[oc][m]*w1[m][ic][tap], tf32
// ---------------------------------------------------------------------------
__global__ __launch_bounds__(256) void fuse_w(const float* __restrict__ w1,
                                              const float* __restrict__ w2) {
    const int tap = blockIdx.x;
    const int ic = threadIdx.x;
    __shared__ float w2s[OC2 * 128];
    for (int i = threadIdx.x; i < OC2 * 128; i += 256) w2s[i] = w2[i];
    __syncthreads();

    float acc[OC2];
#pragma unroll
    for (int k = 0; k < OC2; k++) acc[k] = 0.f;
    const float* w1p = w1 + ic * 49 + tap;
#pragma unroll 2
    for (int m = 0; m < 128; m++) {
        float a = __ldg(w1p + (size_t)m * KTOT);
#pragma unroll
        for (int k = 0; k < OC2; k++) acc[k] = fmaf(a, w2s[k * 128 + m], acc[k]);
    }
    for (int k = 0; k < OC2; k++)
        g_w12t[(size_t)k * KTOT + tap * 256 + ic] = to_tf32(acc[k]);
    for (int k = OC2; k < 64; k++)
        g_w12t[(size_t)k * KTOT + tap * 256 + ic] = 0.f;
}

__global__ void bias_fuse(const float* __restrict__ w2,
                          const float* __restrict__ b1,
                          const float* __restrict__ b2) {
    int oc = threadIdx.x;
    if (oc < OC2) {
        float s = b2[oc];
        for (int m = 0; m < 128; m++) s = fmaf(w2[oc * 128 + m], b1[m], s);
        g_b12[oc] = s;
    }
}

// ---------------------------------------------------------------------------
// tf32 mma.sync implicit-GEMM conv + fused bias + softmax.
// CTA: M=128 px (2 rows x 64 cols), N=64 oc, K=12544 in 196 chunks of 64.
// 8 warps, 4x2 warp grid, 32x32 warp tiles. 3-stage cp.async pipeline.
// ---------------------------------------------------------------------------
__global__ __launch_bounds__(256) void conv_mma() {
    extern __shared__ __align__(16) char smem[];
    const uint32_t sbase = smem_u32(smem);
    const int tid = threadIdx.x, wid = tid >> 5, lane = tid & 31;
    const int gid = lane >> 2, tg = lane & 3;
    const int hr0 = blockIdx.x * 2, b = blockIdx.y;
    const int mbase = (wid >> 1) * 32, nbase = (wid & 1) * 32;

    float acc[2][4][4];
#pragma unroll
    for (int mt = 0; mt < 2; mt++)
#pragma unroll
        for (int nt = 0; nt < 4; nt++)
#pragma unroll
            for (int r = 0; r < 4; r++) acc[mt][nt][r] = 0.f;

    int aoff[4], boff[4];
#pragma unroll
    for (int j = 0; j < 4; j++) {
        aoff[j] = (mbase + gid + 8 * j) * ASTRIDE + tg;
        boff[j] = (nbase + gid + 8 * j) * ASTRIDE + tg;
    }

    const float* xb = g_xn + (size_t)b * XP * XP * CIN;

#define COPY_CHUNK(q, st) do {                                                  \
    const int _tap = (q) >> 2, _icb = (q) & 3;                                  \
    const int _u = _tap / 7, _v = _tap - _u * 7;                                \
    const float* _as = xb + (((size_t)(hr0 + 2 * _u)) * XP + 2 * _v) * CIN + _icb * 64; \
    const float* _bs = g_w12t + (size_t)_tap * 256 + (size_t)_icb * 64;         \
    const uint32_t _da = sbase + (st) * STAGE;                                  \
    const uint32_t _db = _da + STG_A;                                           \
    for (int _i = tid; _i < 3072; _i += 256) {                                  \
        if (_i < 2048) {                                                        \
            int _px = _i >> 4, _j = _i & 15;                                    \
            int _pr = _px >> 6, _pc = _px & 63;                                 \
            cp16(_da + _px * (ASTRIDE * 4) + _j * 16,                           \
                 _as + ((size_t)_pr * XP + _pc) * CIN + _j * 4);                \
        } else {                                                                \
            int _t = _i - 2048;                                                 \
            int _oc = _t >> 4, _j = _t & 15;                                    \
            cp16(_db + _oc * (ASTRIDE * 4) + _j * 16,                           \
                 _bs + (size_t)_oc * KTOT + _j * 4);                            \
        }                                                                       \
    }                                                                           \
} while (0)

    COPY_CHUNK(0, 0); CP_COMMIT();
    COPY_CHUNK(1, 1); CP_COMMIT();
    COPY_CHUNK(2, 2); CP_COMMIT();

#pragma unroll 1
    for (int q = 0; q < NQ; q++) {
        CP_WAIT(2);
        __syncthreads();
        const int st = q % 3;
        const float* As = (const float*)(smem + st * STAGE);
        const float* Bs = (const float*)(smem + st * STAGE + STG_A);
#pragma unroll
        for (int ks = 0; ks < 8; ks++) {
            const int k8 = ks * 8;
            uint32_t A0[4], A4[4], B0[4], B4[4];
#pragma unroll
            for (int j = 0; j < 4; j++) {
                A0[j] = __float_as_uint(As[aoff[j] + k8]);
                A4[j] = __float_as_uint(As[aoff[j] + k8 + 4]);
                B0[j] = __float_as_uint(Bs[boff[j] + k8]);
                B4[j] = __float_as_uint(Bs[boff[j] + k8 + 4]);
            }
#pragma unroll
            for (int mt = 0; mt < 2; mt++)
#pragma unroll
                for (int nt = 0; nt < 4; nt++)
                    mma_tf32(acc[mt][nt], A0[2 * mt], A0[2 * mt + 1],
                             A4[2 * mt], A4[2 * mt + 1], B0[nt], B4[nt]);
        }
        __syncthreads();
        if (q + 3 < NQ) { COPY_CHUNK(q + 3, st); }
        CP_COMMIT();                       // empty-group in tail keeps invariant
    }

    // ---------------- epilogue: logits -> smem -> softmax -> g_attn ----------
    __syncthreads();
    float* lg = (float*)smem;              // [128][66]
#pragma unroll
    for (int mt = 0; mt < 2; mt++) {
        const int row0 = mbase + mt * 16 + gid;
#pragma unroll
        for (int nt = 0; nt < 4; nt++) {
            const int col = nbase + nt * 8 + tg * 2;
            *(float2*)&lg[row0 * 66 + col] =
                make_float2(acc[mt][nt][0], acc[mt][nt][1]);
            *(float2*)&lg[(row0 + 8) * 66 + col] =
                make_float2(acc[mt][nt][2], acc[mt][nt][3]);
        }
    }
    __syncthreads();
    if (tid < 128) {
        const float* p = lg + tid * 66;
        float e[OC2];
        float mx = -1e30f;
#pragma unroll
        for (int k = 0; k < OC2; k++) {
            e[k] = p[k] + __ldg(&g_b12[k]);
            mx = fmaxf(mx, e[k]);
        }
        float s = 0.f;
#pragma unroll
        for (int k = 0; k < OC2; k++) { e[k] = __expf(e[k] - mx); s += e[k]; }
        const float inv = 1.f / s;
        const int h = hr0 + (tid >> 6), w = tid & 63;
        float* dst = g_attn + ((size_t)(b * OC2) * HH + h) * WW + w;
#pragma unroll
        for (int k = 0; k < OC2; k++)
            dst[(size_t)k * (HH * WW)] = e[k] * inv;
    }
#undef COPY_CHUNK
}

// ---------------------------------------------------------------------------
// Gather: out[b,c,h,w] = sum_k attn[b,k,h,w] * xpad[b,c,h+2u,w+2v]
// 256 threads = 2 sub-blocks of 128 px-lanes, 3-buffer cp.async pipeline.
// ---------------------------------------------------------------------------
__global__ __launch_bounds__(256) void gather_kernel(float* __restrict__ out) {
    const int tile = blockIdx.x;                 // 8 h-tiles x 4 w-tiles
    const int h0 = (tile >> 2) * 8, w0 = (tile & 3) * 16;
    const int b = blockIdx.z;
    const int tid = threadIdx.x;
    const int sub = tid >> 7, stid = tid & 127;
    const int rr = stid >> 4, cc = stid & 15;
    const int h = h0 + rr, w = w0 + cc;
    const int c0 = blockIdx.y * 128 + sub * 64;

    __shared__ __align__(16) float xsm[3][2][20 * GSTRIDE];

    float attn[OC2];
#pragma unroll
    for (int k = 0; k < OC2; k++)
        attn[k] = g_attn[(((size_t)(b * OC2 + k)) * HH + h) * WW + w];

    uint32_t sb[3];
#pragma unroll
    for (int s = 0; s < 3; s++) sb[s] = smem_u32(&xsm[s][sub][0]);

    const float* plane0 = g_xpad + (((size_t)(b * CIN + c0)) * XP + h0) * XP + w0;

#define CPCH(c, st) do {                                                        \
    const float* _src = plane0 + (size_t)(c) * XP * XP;                         \
    for (int _i = stid; _i < 140; _i += 128) {                                  \
        int _r = _i / 7, _j = _i - _r * 7;                                      \
        cp16(sb[st] + (_r * GSTRIDE + _j * 4) * 4, _src + _r * XP + _j * 4);    \
    }                                                                           \
} while (0)

    CPCH(0, 0); CP_COMMIT();
    CPCH(1, 1); CP_COMMIT();

#pragma unroll 1
    for (int c = 0; c < 64; c++) {
        CP_WAIT(1);
        __syncthreads();
        if (c + 2 < 64) { CPCH(c + 2, (c + 2) % 3); }
        CP_COMMIT();

        const float* xs = &xsm[c % 3][sub][0];
        float o = 0.f;
#pragma unroll
        for (int u = 0; u < 7; u++)
#pragma unroll
            for (int v = 0; v < 7; v++)
                o = fmaf(attn[u * 7 + v], xs[(rr + 2 * u) * GSTRIDE + cc + 2 * v], o);

        out[(((size_t)(b * CIN + c0 + c)) * HH + h) * WW + w] = o;
    }
#undef CPCH
}

// ---------------------------------------------------------------------------
extern "C" void kernel_launch(void* const* d_in, const int* in_sizes, int n_in,
                              void* d_out, int out_size)
{
    const float* x  = (const float*)d_in[0];
    const float* w1 = (const float*)d_in[1];
    const float* b1 = (const float*)d_in[2];
    const float* w2 = (const float*)d_in[3];
    const float* b2 = (const float*)d_in[4];
    float* out = (float*)d_out;

    cudaFuncSetAttribute(conv_mma, cudaFuncAttributeMaxDynamicSharedMemorySize,
                         SMEM_CONV);

    pad_x<<<dim3(CIN, 4), 256>>>(x);
    nhwc_pad<<<dim3(XP, 4), 256>>>(x);
    fuse_w<<<49, 256>>>(w1, w2);
    bias_fuse<<<1, 64>>>(w2, b1, b2);
    conv_mma<<<dim3(32, 4), 256, SMEM_CONV>>>();
    gather_kernel<<<dim3(32, 2, 4), 256>>>(out);
}

// round 5
// speedup vs baseline: 5.5126x; 1.3804x over previous
#include <cuda_runtime.h>
#include <cstdint>

#define HH 64
#define WW 64
#define CIN 256
#define XP 76
#define OC2 49
#define KTOT 12544              // 49 taps * 256 ic
#define NQ 196                  // K chunks of 64 (28 slabs x 7 v)
#define NSLAB 28
#define RS 68                   // smem row stride (floats): stride%32==4 -> conflict-free
#define SLAB_BYTES (2 * 76 * RS * 4)      // 41344
#define BTILE_BYTES (64 * RS * 4)         // 17408
#define BRING_OFF (2 * SLAB_BYTES)        // 82688
#define SMEM_CONV (2 * SLAB_BYTES + 4 * BTILE_BYTES)   // 152320
#define GSTRIDE 48

// Scratch (device globals: allocation-free, graph-capturable)
__device__ float g_xpad[4 * CIN * XP * XP];      // NCHW padded fp32 (gather)
__device__ float g_xn[4 * XP * XP * CIN];        // NHWC padded tf32-rounded (conv A)
__device__ float g_w12t[64 * KTOT];              // fused W^T [oc64][k], tf32-rounded
__device__ float g_b12[OC2];                     // fused bias (fp32)
__device__ float g_attn[4 * OC2 * HH * WW];      // softmax attention

// ---------------- helpers ----------------
__device__ __forceinline__ uint32_t smem_u32(const void* p) {
    uint32_t a;
    asm("{ .reg .u64 t; cvta.to.shared.u64 t, %1; cvt.u32.u64 %0, t; }" : "=r"(a) : "l"(p));
    return a;
}
__device__ __forceinline__ float to_tf32(float x) {
    uint32_t u;
    asm("cvt.rna.tf32.f32 %0, %1;" : "=r"(u) : "f"(x));
    return __uint_as_float(u);
}
__device__ __forceinline__ void cp16(uint32_t d, const void* s) {
    asm volatile("cp.async.cg.shared.global [%0], [%1], 16;" :: "r"(d), "l"(s));
}
#define CP_COMMIT() asm volatile("cp.async.commit_group;")
#define CP_WAIT(n)  asm volatile("cp.async.wait_group %0;" :: "n"(n))

__device__ __forceinline__ void mma_tf32(float* c, uint32_t a0, uint32_t a1,
                                         uint32_t a2, uint32_t a3,
                                         uint32_t b0, uint32_t b1) {
    asm volatile(
        "mma.sync.aligned.m16n8k8.row.col.f32.tf32.tf32.f32 "
        "{%0,%1,%2,%3},{%4,%5,%6,%7},{%8,%9},{%0,%1,%2,%3};"
        : "+f"(c[0]), "+f"(c[1]), "+f"(c[2]), "+f"(c[3])
        : "r"(a0), "r"(a1), "r"(a2), "r"(a3), "r"(b0), "r"(b1));
}

// ---------------------------------------------------------------------------
// NCHW zero-padded copy (fp32, for gather)
// ---------------------------------------------------------------------------
__global__ __launch_bounds__(256) void pad_x(const float* __restrict__ x) {
    const int c = blockIdx.x, b = blockIdx.y;
    float* dst = g_xpad + ((size_t)(b * CIN + c)) * XP * XP;
    const float* src = x + ((size_t)(b * CIN + c)) * HH * WW;
    for (int idx = threadIdx.x; idx < XP * XP; idx += 256) {
        int r = idx / XP, cc = idx - r * XP;
        float v = 0.f;
        if (r >= 6 && r < 70 && cc >= 6 && cc < 70)
            v = src[(r - 6) * WW + (cc - 6)];
        dst[idx] = v;
    }
}

// ---------------------------------------------------------------------------
// NHWC zero-padded transpose with tf32 rounding: g_xn[b][r][c][ic]
// ---------------------------------------------------------------------------
__global__ __launch_bounds__(256) void nhwc_pad(const float* __restrict__ x) {
    const int r = blockIdx.x, b = blockIdx.y;
    float* outr = g_xn + (((size_t)b * XP + r)) * XP * CIN;
    if (r < 6 || r >= 70) {
        for (int i = threadIdx.x; i < XP * CIN; i += 256) outr[i] = 0.f;
        return;
    }
    const int h = r - 6;
    __shared__ float sm[128 * 65];
    for (int half = 0; half < 2; half++) {
        const int ich = half * 128;
        for (int idx = threadIdx.x; idx < 128 * 64; idx += 256) {
            int icl = idx >> 6, w = idx & 63;
            sm[icl * 65 + w] = x[(((size_t)(b * CIN + ich + icl)) * HH + h) * WW + w];
        }
        __syncthreads();
        for (int idx = threadIdx.x; idx < 64 * 128; idx += 256) {
            int w = idx >> 7, icl = idx & 127;
            outr[(size_t)(w + 6) * CIN + ich + icl] = to_tf32(sm[icl * 65 + w]);
        }
        __syncthreads();
    }
    for (int idx = threadIdx.x; idx < 12 * CIN; idx += 256) {
        int cb = idx >> 8, ic = idx & 255;
        int c = (cb < 6) ? cb : cb + 64;
        outr[(size_t)c * CIN + ic] = 0.f;
    }
}

// ---------------------------------------------------------------------------
// Fused weights: g_w12t[oc][tap*256+ic] = sum_m w2[oc][m]*w1[m][ic][tap], tf32
// ---------------------------------------------------------------------------
__global__ __launch_bounds__(256) void fuse_w(const float* __restrict__ w1,
                                              const float* __restrict__ w2) {
    const int tap = blockIdx.x;
    const int ic = threadIdx.x;
    __shared__ float w2s[OC2 * 128];
    for (int i = threadIdx.x; i < OC2 * 128; i += 256) w2s[i] = w2[i];
    __syncthreads();

    float acc[OC2];
#pragma unroll
    for (int k = 0; k < OC2; k++) acc[k] = 0.f;
    const float* w1p = w1 + ic * 49 + tap;
#pragma unroll 2
    for (int m = 0; m < 128; m++) {
        float a = __ldg(w1p + (size_t)m * KTOT);
#pragma unroll
        for (int k = 0; k < OC2; k++) acc[k] = fmaf(a, w2s[k * 128 + m], acc[k]);
    }
    for (int k = 0; k < OC2; k++)
        g_w12t[(size_t)k * KTOT + tap * 256 + ic] = to_tf32(acc[k]);
    for (int k = OC2; k < 64; k++)
        g_w12t[(size_t)k * KTOT + tap * 256 + ic] = 0.f;
}

__global__ __launch_bounds__(128) void bias_fuse(const float* __restrict__ w2,
                                                 const float* __restrict__ b1,
                                                 const float* __restrict__ b2) {
    const int oc = blockIdx.x, tid = threadIdx.x;
    float v = w2[oc * 128 + tid] * b1[tid];
#pragma unroll
    for (int off = 16; off > 0; off >>= 1)
        v += __shfl_xor_sync(0xFFFFFFFFu, v, off);
    __shared__ float ws[4];
    if ((tid & 31) == 0) ws[tid >> 5] = v;
    __syncthreads();
    if (tid == 0) g_b12[oc] = ws[0] + ws[1] + ws[2] + ws[3] + b2[oc];
}

// ---------------------------------------------------------------------------
// tf32 mma.sync implicit-GEMM conv + fused bias + softmax.
// CTA: M=128 px (2 rows x 64 cols), N=64 oc. 28 slabs x 7 v-chunks (K=64 each).
// A staged once per slab (2x76x64ic, reused by 7 v via fragment offset).
// 2-slab A ring + 4-slot B ring, one cp.async group per chunk.
// ---------------------------------------------------------------------------
__global__ __launch_bounds__(256) void conv_mma() {
    extern __shared__ __align__(16) char smem[];
    const uint32_t sbase = smem_u32(smem);
    const int tid = threadIdx.x, wid = tid >> 5, lane = tid & 31;
    const int gid = lane >> 2, tg = lane & 3;
    const int hr0 = blockIdx.x * 2, b = blockIdx.y;
    const int mbase = (wid >> 1) * 32, nbase = (wid & 1) * 32;

    float acc[2][4][4];
#pragma unroll
    for (int mt = 0; mt < 2; mt++)
#pragma unroll
        for (int nt = 0; nt < 4; nt++)
#pragma unroll
            for (int r = 0; r < 4; r++) acc[mt][nt][r] = 0.f;

    // A fragment row bases in slab coords: (pr*76 + (m&63)) for m = mbase+gid+8j
    int arow68[4], boff[4];
#pragma unroll
    for (int j = 0; j < 4; j++) {
        arow68[j] = ((mbase >> 6) * 76 + (mbase & 63) + gid + 8 * j) * RS + tg;
        boff[j] = (nbase + gid + 8 * j) * RS + tg;
    }

    const float* xb = g_xn + (size_t)b * XP * XP * CIN;

#define COPY_SLAB(s, slot) do {                                                 \
    const int _u = (s) >> 2, _icb = (s) & 3;                                    \
    const float* _src = xb + ((size_t)(hr0 + 2 * _u) * XP) * CIN + _icb * 64;   \
    const uint32_t _dst = sbase + (slot) * SLAB_BYTES;                          \
    for (int _i = tid; _i < 2432; _i += 256) {                                  \
        int _row = _i >> 4, _j = _i & 15;                                       \
        int _pr = _row / 76, _col = _row - _pr * 76;                            \
        cp16(_dst + _row * (RS * 4) + _j * 16,                                  \
             _src + ((size_t)_pr * XP + _col) * CIN + _j * 4);                  \
    }                                                                           \
} while (0)

#define COPY_B(q, slot) do {                                                    \
    const int _s = (q) / 7, _v = (q) - _s * 7;                                  \
    const int _tap = (_s >> 2) * 7 + _v, _icb = _s & 3;                         \
    const float* _bs = g_w12t + _tap * 256 + _icb * 64;                         \
    const uint32_t _dst = sbase + BRING_OFF + (slot) * BTILE_BYTES;             \
    for (int _i = tid; _i < 1024; _i += 256) {                                  \
        int _oc = _i >> 4, _j = _i & 15;                                        \
        cp16(_dst + _oc * (RS * 4) + _j * 16, _bs + (size_t)_oc * KTOT + _j * 4); \
    }                                                                           \
} while (0)

    COPY_SLAB(0, 0); COPY_B(0, 0); CP_COMMIT();
    COPY_SLAB(1, 1); COPY_B(1, 1); CP_COMMIT();
    COPY_B(2, 2); CP_COMMIT();

#pragma unroll 1
    for (int q = 0; q < NQ; q++) {
        CP_WAIT(2);
        __syncthreads();
        const int s = q / 7, v = q - s * 7;
        const float* As = (const float*)(smem + (s & 1) * SLAB_BYTES);
        const float* Bs = (const float*)(smem + BRING_OFF + (q & 3) * BTILE_BYTES);
        int aoff[4];
#pragma unroll
        for (int j = 0; j < 4; j++) aoff[j] = arow68[j] + v * (2 * RS);
#pragma unroll
        for (int ks = 0; ks < 8; ks++) {
            const int k8 = ks * 8;
            uint32_t A0[4], A4[4], B0[4], B4[4];
#pragma unroll
            for (int j = 0; j < 4; j++) {
                A0[j] = __float_as_uint(As[aoff[j] + k8]);
                A4[j] = __float_as_uint(As[aoff[j] + k8 + 4]);
                B0[j] = __float_as_uint(Bs[boff[j] + k8]);
                B4[j] = __float_as_uint(Bs[boff[j] + k8 + 4]);
            }
#pragma unroll
            for (int mt = 0; mt < 2; mt++)
#pragma unroll
                for (int nt = 0; nt < 4; nt++)
                    mma_tf32(acc[mt][nt], A0[2 * mt], A0[2 * mt + 1],
                             A4[2 * mt], A4[2 * mt + 1], B0[nt], B4[nt]);
        }
        __syncthreads();
        if (v == 0 && s >= 1 && s + 1 < NSLAB) COPY_SLAB(s + 1, (s + 1) & 1);
        if (q + 3 < NQ) COPY_B(q + 3, (q + 3) & 3);
        CP_COMMIT();                        // exactly one group per iteration
    }
    CP_WAIT(0);

    // ---------------- epilogue: logits -> smem -> softmax -> g_attn ----------
    __syncthreads();
    float* lg = (float*)smem;               // [128][66]
#pragma unroll
    for (int mt = 0; mt < 2; mt++) {
        const int row0 = mbase + mt * 16 + gid;
#pragma unroll
        for (int nt = 0; nt < 4; nt++) {
            const int col = nbase + nt * 8 + tg * 2;
            *(float2*)&lg[row0 * 66 + col] =
                make_float2(acc[mt][nt][0], acc[mt][nt][1]);
            *(float2*)&lg[(row0 + 8) * 66 + col] =
                make_float2(acc[mt][nt][2], acc[mt][nt][3]);
        }
    }
    __syncthreads();
    if (tid < 128) {
        const float* p = lg + tid * 66;
        float e[OC2];
        float mx = -1e30f;
#pragma unroll
        for (int k = 0; k < OC2; k++) {
            e[k] = p[k] + __ldg(&g_b12[k]);
            mx = fmaxf(mx, e[k]);
        }
        float s = 0.f;
#pragma unroll
        for (int k = 0; k < OC2; k++) { e[k] = __expf(e[k] - mx); s += e[k]; }
        const float inv = 1.f / s;
        const int h = hr0 + (tid >> 6), w = tid & 63;
        float* dst = g_attn + ((size_t)(b * OC2) * HH + h) * WW + w;
#pragma unroll
        for (int k = 0; k < OC2; k++)
            dst[(size_t)k * (HH * WW)] = e[k] * inv;
    }
#undef COPY_SLAB
#undef COPY_B
}

// ---------------------------------------------------------------------------
// Gather: out[b,c,h,w] = sum_k attn[b,k,h,w] * xpad[b,c,h+2u,w+2v]
// 256 threads = 2 sub-blocks of 128 px-lanes, 3-buffer cp.async pipeline.
// ---------------------------------------------------------------------------
__global__ __launch_bounds__(256) void gather_kernel(float* __restrict__ out) {
    const int tile = blockIdx.x;                 // 8 h-tiles x 4 w-tiles
    const int h0 = (tile >> 2) * 8, w0 = (tile & 3) * 16;
    const int b = blockIdx.z;
    const int tid = threadIdx.x;
    const int sub = tid >> 7, stid = tid & 127;
    const int rr = stid >> 4, cc = stid & 15;
    const int h = h0 + rr, w = w0 + cc;
    const int c0 = blockIdx.y * 128 + sub * 64;

    __shared__ __align__(16) float xsm[3][2][20 * GSTRIDE];

    float attn[OC2];
#pragma unroll
    for (int k = 0; k < OC2; k++)
        attn[k] = g_attn[(((size_t)(b * OC2 + k)) * HH + h) * WW + w];

    uint32_t sb[3];
#pragma unroll
    for (int s = 0; s < 3; s++) sb[s] = smem_u32(&xsm[s][sub][0]);

    const float* plane0 = g_xpad + (((size_t)(b * CIN + c0)) * XP + h0) * XP + w0;

#define CPCH(c, st) do {                                                        \
    const float* _src = plane0 + (size_t)(c) * XP * XP;                         \
    for (int _i = stid; _i < 140; _i += 128) {                                  \
        int _r = _i / 7, _j = _i - _r * 7;                                      \
        cp16(sb[st] + (_r * GSTRIDE + _j * 4) * 4, _src + _r * XP + _j * 4);    \
    }                                                                           \
} while (0)

    CPCH(0, 0); CP_COMMIT();
    CPCH(1, 1); CP_COMMIT();

#pragma unroll 1
    for (int c = 0; c < 64; c++) {
        CP_WAIT(1);
        __syncthreads();
        if (c + 2 < 64) { CPCH(c + 2, (c + 2) % 3); }
        CP_COMMIT();

        const float* xs = &xsm[c % 3][sub][0];
        float o = 0.f;
#pragma unroll
        for (int u = 0; u < 7; u++)
#pragma unroll
            for (int v = 0; v < 7; v++)
                o = fmaf(attn[u * 7 + v], xs[(rr + 2 * u) * GSTRIDE + cc + 2 * v], o);

        out[(((size_t)(b * CIN + c0 + c)) * HH + h) * WW + w] = o;
    }
#undef CPCH
}

// ---------------------------------------------------------------------------
extern "C" void kernel_launch(void* const* d_in, const int* in_sizes, int n_in,
                              void* d_out, int out_size)
{
    const float* x  = (const float*)d_in[0];
    const float* w1 = (const float*)d_in[1];
    const float* b1 = (const float*)d_in[2];
    const float* w2 = (const float*)d_in[3];
    const float* b2 = (const float*)d_in[4];
    float* out = (float*)d_out;

    cudaFuncSetAttribute(conv_mma, cudaFuncAttributeMaxDynamicSharedMemorySize,
                         SMEM_CONV);

    pad_x<<<dim3(CIN, 4), 256>>>(x);
    nhwc_pad<<<dim3(XP, 4), 256>>>(x);
    fuse_w<<<49, 256>>>(w1, w2);
    bias_fuse<<<49, 128>>>(w2, b1, b2);
    conv_mma<<<dim3(32, 4), 256, SMEM_CONV>>>();
    gather_kernel<<<dim3(32, 2, 4), 256>>>(out);
}

// round 6
// speedup vs baseline: 7.4241x; 1.3468x over previous
#include <cuda_runtime.h>
#include <cuda_fp16.h>
#include <cstdint>

#define HH 64
#define WW 64
#define CIN 256
#define XP 76
#define OC2 49
#define KTOT 12544              // 49 taps * 256 ic (halves in g_w12t)
#define NQ 196                  // K chunks of 64 (28 slabs x 7 v)
#define NSLAB 28
#define RSH 72                  // smem row stride (halves): 36 words % 32 == 4 -> conflict-free
#define SLAB_BYTES (152 * RSH * 2)        // 21888
#define BTILE_BYTES (64 * RSH * 2)        // 9216
#define BRING_OFF (2 * SLAB_BYTES)        // 43776
#define SMEM_CONV (2 * SLAB_BYTES + 4 * BTILE_BYTES)   // 80640
#define GSTRIDE 48

// Scratch (device globals: allocation-free, graph-capturable)
__device__ float  g_xpad[4 * CIN * XP * XP];     // NCHW padded fp32 (gather)
__device__ __half g_xn[4 * XP * XP * CIN];       // NHWC padded fp16 (conv A)
__device__ __half g_w12t[64 * KTOT];             // fused W^T [oc64][k], fp16
__device__ float  g_b12[OC2];                    // fused bias (fp32)
__device__ float  g_attn[4 * OC2 * HH * WW];     // softmax attention

// ---------------- helpers ----------------
__device__ __forceinline__ uint32_t smem_u32(const void* p) {
    uint32_t a;
    asm("{ .reg .u64 t; cvta.to.shared.u64 t, %1; cvt.u32.u64 %0, t; }" : "=r"(a) : "l"(p));
    return a;
}
__device__ __forceinline__ void cp16(uint32_t d, const void* s) {
    asm volatile("cp.async.cg.shared.global [%0], [%1], 16;" :: "r"(d), "l"(s));
}
#define CP_COMMIT() asm volatile("cp.async.commit_group;")
#define CP_WAIT(n)  asm volatile("cp.async.wait_group %0;" :: "n"(n))

// m16n8k16 fp16 inputs, fp32 accumulate
__device__ __forceinline__ void mma_f16(float* c, uint32_t a0, uint32_t a1,
                                        uint32_t a2, uint32_t a3,
                                        uint32_t b0, uint32_t b1) {
    asm volatile(
        "mma.sync.aligned.m16n8k16.row.col.f32.f16.f16.f32 "
        "{%0,%1,%2,%3},{%4,%5,%6,%7},{%8,%9},{%0,%1,%2,%3};"
        : "+f"(c[0]), "+f"(c[1]), "+f"(c[2]), "+f"(c[3])
        : "r"(a0), "r"(a1), "r"(a2), "r"(a3), "r"(b0), "r"(b1));
}

// ---------------------------------------------------------------------------
// NCHW zero-padded copy (fp32, for gather)
// ---------------------------------------------------------------------------
__global__ __launch_bounds__(256) void pad_x(const float* __restrict__ x) {
    const int c = blockIdx.x, b = blockIdx.y;
    float* dst = g_xpad + ((size_t)(b * CIN + c)) * XP * XP;
    const float* src = x + ((size_t)(b * CIN + c)) * HH * WW;
    for (int idx = threadIdx.x; idx < XP * XP; idx += 256) {
        int r = idx / XP, cc = idx - r * XP;
        float v = 0.f;
        if (r >= 6 && r < 70 && cc >= 6 && cc < 70)
            v = src[(r - 6) * WW + (cc - 6)];
        dst[idx] = v;
    }
}

// ---------------------------------------------------------------------------
// NHWC zero-padded transpose to fp16: g_xn[b][r][c][ic]
// ---------------------------------------------------------------------------
__global__ __launch_bounds__(256) void nhwc_pad(const float* __restrict__ x) {
    const int r = blockIdx.x, b = blockIdx.y;
    __half* outr = g_xn + (((size_t)b * XP + r)) * XP * CIN;
    if (r < 6 || r >= 70) {
        for (int i = threadIdx.x; i < XP * CIN; i += 256) outr[i] = __half(0);
        return;
    }
    const int h = r - 6;
    __shared__ float sm[128 * 65];
    for (int half_i = 0; half_i < 2; half_i++) {
        const int ich = half_i * 128;
        for (int idx = threadIdx.x; idx < 128 * 64; idx += 256) {
            int icl = idx >> 6, w = idx & 63;
            sm[icl * 65 + w] = x[(((size_t)(b * CIN + ich + icl)) * HH + h) * WW + w];
        }
        __syncthreads();
        for (int idx = threadIdx.x; idx < 64 * 128; idx += 256) {
            int w = idx >> 7, icl = idx & 127;
            outr[(size_t)(w + 6) * CIN + ich + icl] = __float2half_rn(sm[icl * 65 + w]);
        }
        __syncthreads();
    }
    for (int idx = threadIdx.x; idx < 12 * CIN; idx += 256) {
        int cb = idx >> 8, ic = idx & 255;
        int c = (cb < 6) ? cb : cb + 64;
        outr[(size_t)c * CIN + ic] = __half(0);
    }
}

// ---------------------------------------------------------------------------
// Fused weights: g_w12t[oc][tap*256+ic] = fp16(sum_m w2[oc][m]*w1[m][ic][tap])
// ---------------------------------------------------------------------------
__global__ __launch_bounds__(256) void fuse_w(const float* __restrict__ w1,
                                              const float* __restrict__ w2) {
    const int tap = blockIdx.x;
    const int ic = threadIdx.x;
    __shared__ float w2s[OC2 * 128];
    for (int i = threadIdx.x; i < OC2 * 128; i += 256) w2s[i] = w2[i];
    __syncthreads();

    float acc[OC2];
#pragma unroll
    for (int k = 0; k < OC2; k++) acc[k] = 0.f;
    const float* w1p = w1 + ic * 49 + tap;
#pragma unroll 2
    for (int m = 0; m < 128; m++) {
        float a = __ldg(w1p + (size_t)m * KTOT);
#pragma unroll
        for (int k = 0; k < OC2; k++) acc[k] = fmaf(a, w2s[k * 128 + m], acc[k]);
    }
    for (int k = 0; k < OC2; k++)
        g_w12t[(size_t)k * KTOT + tap * 256 + ic] = __float2half_rn(acc[k]);
    for (int k = OC2; k < 64; k++)
        g_w12t[(size_t)k * KTOT + tap * 256 + ic] = __half(0);
}

__global__ __launch_bounds__(128) void bias_fuse(const float* __restrict__ w2,
                                                 const float* __restrict__ b1,
                                                 const float* __restrict__ b2) {
    const int oc = blockIdx.x, tid = threadIdx.x;
    float v = w2[oc * 128 + tid] * b1[tid];
#pragma unroll
    for (int off = 16; off > 0; off >>= 1)
        v += __shfl_xor_sync(0xFFFFFFFFu, v, off);
    __shared__ float ws[4];
    if ((tid & 31) == 0) ws[tid >> 5] = v;
    __syncthreads();
    if (tid == 0) g_b12[oc] = ws[0] + ws[1] + ws[2] + ws[3] + b2[oc];
}

// ---------------------------------------------------------------------------
// fp16 mma.sync implicit-GEMM conv + fused bias + softmax.
// CTA: M=128 px (2 rows x 64 cols), N=64 oc. 28 slabs x 7 v-chunks (K=64 each).
// A staged once per slab (fp16, 2x76x64ic), 2-slab ring + 4-slot B ring.
// ---------------------------------------------------------------------------
__global__ __launch_bounds__(256) void conv_mma() {
    extern __shared__ __align__(16) char smem[];
    const uint32_t sbase = smem_u32(smem);
    const int tid = threadIdx.x, wid = tid >> 5, lane = tid & 31;
    const int gid = lane >> 2, tg = lane & 3;
    const int hr0 = blockIdx.x * 2, b = blockIdx.y;
    const int mbase = (wid >> 1) * 32, nbase = (wid & 1) * 32;

    float acc[2][4][4];
#pragma unroll
    for (int mt = 0; mt < 2; mt++)
#pragma unroll
        for (int nt = 0; nt < 4; nt++)
#pragma unroll
            for (int r = 0; r < 4; r++) acc[mt][nt][r] = 0.f;

    // A fragment row bases (half units) in slab coords; B offsets
    int arow[4], boff[4];
#pragma unroll
    for (int j = 0; j < 4; j++) {
        arow[j] = ((mbase >> 6) * 76 + (mbase & 63) + gid + 8 * j) * RSH + 2 * tg;
        boff[j] = (nbase + 8 * j + gid) * RSH + 2 * tg;
    }

    const __half* xb = g_xn + (size_t)b * XP * XP * CIN;

#define COPY_SLAB(s, slot) do {                                                 \
    const int _u = (s) >> 2, _icb = (s) & 3;                                    \
    const __half* _src = xb + ((size_t)(hr0 + 2 * _u) * XP) * CIN + _icb * 64;  \
    const uint32_t _dst = sbase + (slot) * SLAB_BYTES;                          \
    for (int _i = tid; _i < 1216; _i += 256) {                                  \
        int _row = _i >> 3, _j = _i & 7;                                        \
        int _pr = _row / 76, _col = _row - _pr * 76;                            \
        cp16(_dst + _row * (RSH * 2) + _j * 16,                                 \
             _src + ((size_t)_pr * XP + _col) * CIN + _j * 8);                  \
    }                                                                           \
} while (0)

#define COPY_B(q, slot) do {                                                    \
    const int _s = (q) / 7, _v = (q) - _s * 7;                                  \
    const int _tap = (_s >> 2) * 7 + _v, _icb = _s & 3;                         \
    const __half* _bs = g_w12t + _tap * 256 + _icb * 64;                        \
    const uint32_t _dst = sbase + BRING_OFF + (slot) * BTILE_BYTES;             \
    for (int _i = tid; _i < 512; _i += 256) {                                   \
        int _oc = _i >> 3, _j = _i & 7;                                         \
        cp16(_dst + _oc * (RSH * 2) + _j * 16, _bs + (size_t)_oc * KTOT + _j * 8); \
    }                                                                           \
} while (0)

    COPY_SLAB(0, 0); COPY_B(0, 0); CP_COMMIT();
    COPY_SLAB(1, 1); COPY_B(1, 1); CP_COMMIT();
    COPY_B(2, 2); CP_COMMIT();

#pragma unroll 1
    for (int q = 0; q < NQ; q++) {
        CP_WAIT(2);
        __syncthreads();
        const int s = q / 7, v = q - s * 7;
        const __half* As = (const __half*)(smem + (s & 1) * SLAB_BYTES);
        const __half* Bs = (const __half*)(smem + BRING_OFF + (q & 3) * BTILE_BYTES);
        const int voff = v * (2 * RSH);
#pragma unroll
        for (int ks = 0; ks < 4; ks++) {
            const int k0 = ks * 16;
            uint32_t Alo[4], Ahi[4], Blo[4], Bhi[4];
#pragma unroll
            for (int j = 0; j < 4; j++) {
                Alo[j] = *(const uint32_t*)&As[arow[j] + voff + k0];
                Ahi[j] = *(const uint32_t*)&As[arow[j] + voff + k0 + 8];
                Blo[j] = *(const uint32_t*)&Bs[boff[j] + k0];
                Bhi[j] = *(const uint32_t*)&Bs[boff[j] + k0 + 8];
            }
#pragma unroll
            for (int mt = 0; mt < 2; mt++)
#pragma unroll
                for (int nt = 0; nt < 4; nt++)
                    mma_f16(acc[mt][nt], Alo[2 * mt], Alo[2 * mt + 1],
                            Ahi[2 * mt], Ahi[2 * mt + 1], Blo[nt], Bhi[nt]);
        }
        __syncthreads();
        if (v == 0 && s >= 1 && s + 1 < NSLAB) COPY_SLAB(s + 1, (s + 1) & 1);
        if (q + 3 < NQ) COPY_B(q + 3, (q + 3) & 3);
        CP_COMMIT();                        // exactly one group per iteration
    }
    CP_WAIT(0);

    // ---------------- epilogue: logits -> smem -> softmax -> g_attn ----------
    __syncthreads();
    float* lg = (float*)smem;               // [128][66]
#pragma unroll
    for (int mt = 0; mt < 2; mt++) {
        const int row0 = mbase + mt * 16 + gid;
#pragma unroll
        for (int nt = 0; nt < 4; nt++) {
            const int col = nbase + nt * 8 + tg * 2;
            *(float2*)&lg[row0 * 66 + col] =
                make_float2(acc[mt][nt][0], acc[mt][nt][1]);
            *(float2*)&lg[(row0 + 8) * 66 + col] =
                make_float2(acc[mt][nt][2], acc[mt][nt][3]);
        }
    }
    __syncthreads();
    if (tid < 128) {
        const float* p = lg + tid * 66;
        float e[OC2];
        float mx = -1e30f;
#pragma unroll
        for (int k = 0; k < OC2; k++) {
            e[k] = p[k] + __ldg(&g_b12[k]);
            mx = fmaxf(mx, e[k]);
        }
        float s = 0.f;
#pragma unroll
        for (int k = 0; k < OC2; k++) { e[k] = __expf(e[k] - mx); s += e[k]; }
        const float inv = 1.f / s;
        const int h = hr0 + (tid >> 6), w = tid & 63;
        float* dst = g_attn + ((size_t)(b * OC2) * HH + h) * WW + w;
#pragma unroll
        for (int k = 0; k < OC2; k++)
            dst[(size_t)k * (HH * WW)] = e[k] * inv;
    }
#undef COPY_SLAB
#undef COPY_B
}

// ---------------------------------------------------------------------------
// Gather: out[b,c,h,w] = sum_k attn[b,k,h,w] * xpad[b,c,h+2u,w+2v]
// 256 threads = 2 sub-blocks of 128 px-lanes, 3-buffer cp.async pipeline.
// ---------------------------------------------------------------------------
__global__ __launch_bounds__(256) void gather_kernel(float* __restrict__ out) {
    const int tile = blockIdx.x;                 // 8 h-tiles x 4 w-tiles
    const int h0 = (tile >> 2) * 8, w0 = (tile & 3) * 16;
    const int b = blockIdx.z;
    const int tid = threadIdx.x;
    const int sub = tid >> 7, stid = tid & 127;
    const int rr = stid >> 4, cc = stid & 15;
    const int h = h0 + rr, w = w0 + cc;
    const int c0 = blockIdx.y * 128 + sub * 64;

    __shared__ __align__(16) float xsm[3][2][20 * GSTRIDE];

    float attn[OC2];
#pragma unroll
    for (int k = 0; k < OC2; k++)
        attn[k] = g_attn[(((size_t)(b * OC2 + k)) * HH + h) * WW + w];

    uint32_t sb[3];
#pragma unroll
    for (int s = 0; s < 3; s++) sb[s] = smem_u32(&xsm[s][sub][0]);

    const float* plane0 = g_xpad + (((size_t)(b * CIN + c0)) * XP + h0) * XP + w0;

#define CPCH(c, st) do {                                                        \
    const float* _src = plane0 + (size_t)(c) * XP * XP;                         \
    for (int _i = stid; _i < 140; _i += 128) {                                  \
        int _r = _i / 7, _j = _i - _r * 7;                                      \
        cp16(sb[st] + (_r * GSTRIDE + _j * 4) * 4, _src + _r * XP + _j * 4);    \
    }                                                                           \
} while (0)

    CPCH(0, 0); CP_COMMIT();
    CPCH(1, 1); CP_COMMIT();

#pragma unroll 1
    for (int c = 0; c < 64; c++) {
        CP_WAIT(1);
        __syncthreads();
        if (c + 2 < 64) { CPCH(c + 2, (c + 2) % 3); }
        CP_COMMIT();

        const float* xs = &xsm[c % 3][sub][0];
        float o = 0.f;
#pragma unroll
        for (int u = 0; u < 7; u++)
#pragma unroll
            for (int v = 0; v < 7; v++)
                o = fmaf(attn[u * 7 + v], xs[(rr + 2 * u) * GSTRIDE + cc + 2 * v], o);

        out[(((size_t)(b * CIN + c0 + c)) * HH + h) * WW + w] = o;
    }
#undef CPCH
}

// ---------------------------------------------------------------------------
extern "C" void kernel_launch(void* const* d_in, const int* in_sizes, int n_in,
                              void* d_out, int out_size)
{
    const float* x  = (const float*)d_in[0];
    const float* w1 = (const float*)d_in[1];
    const float* b1 = (const float*)d_in[2];
    const float* w2 = (const float*)d_in[3];
    const float* b2 = (const float*)d_in[4];
    float* out = (float*)d_out;

    cudaFuncSetAttribute(conv_mma, cudaFuncAttributeMaxDynamicSharedMemorySize,
                         SMEM_CONV);

    pad_x<<<dim3(CIN, 4), 256>>>(x);
    nhwc_pad<<<dim3(XP, 4), 256>>>(x);
    fuse_w<<<49, 256>>>(w1, w2);
    bias_fuse<<<49, 128>>>(w2, b1, b2);
    conv_mma<<<dim3(32, 4), 256, SMEM_CONV>>>();
    gather_kernel<<<dim3(32, 2, 4), 256>>>(out);
}

// round 7
// speedup vs baseline: 8.3887x; 1.1299x over previous
#include <cuda_runtime.h>
#include <cuda_fp16.h>
#include <cstdint>

#define HH 64
#define WW 64
#define CIN 256
#define XP 76
#define OC2 49
#define KTOT 12544              // 49 taps * 256 ic (halves in g_w12t)
#define NQ 196                  // K chunks of 64 (28 slabs x 7 v)
#define NSLAB 28
#define RSH 72                  // smem row stride (halves): 36 words % 32 == 4 -> conflict-free
#define SLAB_BYTES (152 * RSH * 2)        // 21888
#define BTILE_BYTES (64 * RSH * 2)        // 9216
#define BRING_OFF (2 * SLAB_BYTES)        // 43776
#define SMEM_CONV (2 * SLAB_BYTES + 4 * BTILE_BYTES)   // 80640
#define GSTRIDE 48

// Scratch (device globals: zero-initialized, allocation-free, graph-capturable)
__device__ float  g_xpad[4 * CIN * XP * XP];     // NCHW padded fp32 (gather); borders stay 0
__device__ __half g_xn[4 * XP * XP * CIN];       // NHWC padded fp16 (conv A); borders stay 0
__device__ __half g_w12t[64 * KTOT];             // fused W^T [oc64][k] fp16; oc 49..63 stay 0
__device__ float  g_b12[OC2];                    // fused bias (fp32)
__device__ float  g_attn[4 * OC2 * HH * WW];     // softmax attention

// ---------------- helpers ----------------
__device__ __forceinline__ uint32_t smem_u32(const void* p) {
    uint32_t a;
    asm("{ .reg .u64 t; cvta.to.shared.u64 t, %1; cvt.u32.u64 %0, t; }" : "=r"(a) : "l"(p));
    return a;
}
__device__ __forceinline__ void cp16(uint32_t d, const void* s) {
    asm volatile("cp.async.cg.shared.global [%0], [%1], 16;" :: "r"(d), "l"(s));
}
#define CP_COMMIT() asm volatile("cp.async.commit_group;")
#define CP_WAIT(n)  asm volatile("cp.async.wait_group %0;" :: "n"(n))

// m16n8k16 fp16 inputs, fp32 accumulate
__device__ __forceinline__ void mma_f16(float* c, uint32_t a0, uint32_t a1,
                                        uint32_t a2, uint32_t a3,
                                        uint32_t b0, uint32_t b1) {
    asm volatile(
        "mma.sync.aligned.m16n8k16.row.col.f32.f16.f16.f32 "
        "{%0,%1,%2,%3},{%4,%5,%6,%7},{%8,%9},{%0,%1,%2,%3};"
        : "+f"(c[0]), "+f"(c[1]), "+f"(c[2]), "+f"(c[3])
        : "r"(a0), "r"(a1), "r"(a2), "r"(a3), "r"(b0), "r"(b1));
}
__device__ __forceinline__ void ldm4(uint32_t* r, uint32_t addr) {
    asm volatile("ldmatrix.sync.aligned.m8n8.x4.shared.b16 {%0,%1,%2,%3}, [%4];"
        : "=r"(r[0]), "=r"(r[1]), "=r"(r[2]), "=r"(r[3]) : "r"(addr));
}

// ---------------------------------------------------------------------------
// NCHW padded copy, interior only (borders are zero-initialized globals)
// ---------------------------------------------------------------------------
__global__ __launch_bounds__(256) void pad_x(const float* __restrict__ x) {
    const int c = blockIdx.x, b = blockIdx.y;
    float* dst = g_xpad + ((size_t)(b * CIN + c)) * XP * XP;
    const float* src = x + ((size_t)(b * CIN + c)) * HH * WW;
    for (int idx = threadIdx.x; idx < HH * WW; idx += 256) {
        int r = idx >> 6, cc = idx & 63;
        dst[(r + 6) * XP + cc + 6] = src[idx];
    }
}

// ---------------------------------------------------------------------------
// NHWC transpose to fp16, interior only: g_xn[b][h+6][w+6][ic]
// ---------------------------------------------------------------------------
__global__ __launch_bounds__(256) void nhwc_pad(const float* __restrict__ x) {
    const int h = blockIdx.x, b = blockIdx.y;
    __half* outr = g_xn + (((size_t)b * XP + (h + 6))) * XP * CIN;
    __shared__ float sm[128 * 65];
    for (int half_i = 0; half_i < 2; half_i++) {
        const int ich = half_i * 128;
        for (int idx = threadIdx.x; idx < 128 * 64; idx += 256) {
            int icl = idx >> 6, w = idx & 63;
            sm[icl * 65 + w] = x[(((size_t)(b * CIN + ich + icl)) * HH + h) * WW + w];
        }
        __syncthreads();
        for (int idx = threadIdx.x; idx < 64 * 128; idx += 256) {
            int w = idx >> 7, icl = idx & 127;
            outr[(size_t)(w + 6) * CIN + ich + icl] = __float2half_rn(sm[icl * 65 + w]);
        }
        __syncthreads();
    }
}

// ---------------------------------------------------------------------------
// Fused weights: g_w12t[oc][tap*256+ic] = fp16(sum_m w2[oc][m]*w1[m][ic][tap])
// ---------------------------------------------------------------------------
__global__ __launch_bounds__(256) void fuse_w(const float* __restrict__ w1,
                                              const float* __restrict__ w2) {
    const int tap = blockIdx.x;
    const int ic = threadIdx.x;
    __shared__ float w2s[OC2 * 128];
    for (int i = threadIdx.x; i < OC2 * 128; i += 256) w2s[i] = w2[i];
    __syncthreads();

    float acc[OC2];
#pragma unroll
    for (int k = 0; k < OC2; k++) acc[k] = 0.f;
    const float* w1p = w1 + ic * 49 + tap;
#pragma unroll 2
    for (int m = 0; m < 128; m++) {
        float a = __ldg(w1p + (size_t)m * KTOT);
#pragma unroll
        for (int k = 0; k < OC2; k++) acc[k] = fmaf(a, w2s[k * 128 + m], acc[k]);
    }
    for (int k = 0; k < OC2; k++)
        g_w12t[(size_t)k * KTOT + tap * 256 + ic] = __float2half_rn(acc[k]);
}

__global__ __launch_bounds__(128) void bias_fuse(const float* __restrict__ w2,
                                                 const float* __restrict__ b1,
                                                 const float* __restrict__ b2) {
    const int oc = blockIdx.x, tid = threadIdx.x;
    float v = w2[oc * 128 + tid] * b1[tid];
#pragma unroll
    for (int off = 16; off > 0; off >>= 1)
        v += __shfl_xor_sync(0xFFFFFFFFu, v, off);
    __shared__ float ws[4];
    if ((tid & 31) == 0) ws[tid >> 5] = v;
    __syncthreads();
    if (tid == 0) g_b12[oc] = ws[0] + ws[1] + ws[2] + ws[3] + b2[oc];
}

// ---------------------------------------------------------------------------
// fp16 mma.sync implicit-GEMM conv + fused bias + softmax.
// CTA: M=128 px (2 rows x 64 cols), N=64 oc. 28 slabs x 7 v-chunks (K=64).
// ldmatrix.x4 fragments; copies issued before MMA; one barrier per chunk.
// ---------------------------------------------------------------------------
__global__ __launch_bounds__(256) void conv_mma() {
    extern __shared__ __align__(16) char smem[];
    const uint32_t sbase = smem_u32(smem);
    const int tid = threadIdx.x, wid = tid >> 5, lane = tid & 31;
    const int gid = lane >> 2, tg = lane & 3;
    const int hr0 = blockIdx.x * 2, b = blockIdx.y;
    const int mbase = (wid >> 1) * 32, nbase = (wid & 1) * 32;

    float acc[2][4][4];
#pragma unroll
    for (int mt = 0; mt < 2; mt++)
#pragma unroll
        for (int nt = 0; nt < 4; nt++)
#pragma unroll
            for (int r = 0; r < 4; r++) acc[mt][nt][r] = 0.f;

    // ldmatrix per-lane base offsets (in halves)
    int a_base[2], b_base[2];
    {
        const int l = lane;
        const int rsel = ((l >> 3) & 1) * 8 + (l & 7);
#pragma unroll
        for (int mt = 0; mt < 2; mt++)
            a_base[mt] = ((mbase >> 6) * 76 + (mbase & 63) + mt * 16 + rsel) * RSH
                         + (l >> 4) * 8;
#pragma unroll
        for (int ntp = 0; ntp < 2; ntp++)
            b_base[ntp] = (nbase + ntp * 16 + (l >> 4) * 8 + (l & 7)) * RSH
                          + ((l >> 3) & 1) * 8;
    }

    const __half* xb = g_xn + (size_t)b * XP * XP * CIN;

#define COPY_SLAB(s, slot) do {                                                 \
    const int _u = (s) >> 2, _icb = (s) & 3;                                    \
    const __half* _src = xb + ((size_t)(hr0 + 2 * _u) * XP) * CIN + _icb * 64;  \
    const uint32_t _dst = sbase + (slot) * SLAB_BYTES;                          \
    for (int _i = tid; _i < 1216; _i += 256) {                                  \
        int _row = _i >> 3, _j = _i & 7;                                        \
        int _pr = _row / 76, _col = _row - _pr * 76;                            \
        cp16(_dst + _row * (RSH * 2) + _j * 16,                                 \
             _src + ((size_t)_pr * XP + _col) * CIN + _j * 8);                  \
    }                                                                           \
} while (0)

#define COPY_B(q, slot) do {                                                    \
    const int _s = (q) / 7, _v = (q) - _s * 7;                                  \
    const int _tap = (_s >> 2) * 7 + _v, _icb = _s & 3;                         \
    const __half* _bs = g_w12t + _tap * 256 + _icb * 64;                        \
    const uint32_t _dst = sbase + BRING_OFF + (slot) * BTILE_BYTES;             \
    for (int _i = tid; _i < 512; _i += 256) {                                   \
        int _oc = _i >> 3, _j = _i & 7;                                         \
        cp16(_dst + _oc * (RSH * 2) + _j * 16, _bs + (size_t)_oc * KTOT + _j * 8); \
    }                                                                           \
} while (0)

    COPY_SLAB(0, 0); COPY_B(0, 0); CP_COMMIT();
    COPY_SLAB(1, 1); COPY_B(1, 1); CP_COMMIT();
    COPY_B(2, 2); CP_COMMIT();

#pragma unroll 1
    for (int q = 0; q < NQ; q++) {
        CP_WAIT(2);
        __syncthreads();
        const int s = q / 7, v = q - s * 7;
        // prefetch first: targets are buffers whose readers passed the sync above
        if (v == 0 && s >= 1 && s + 1 < NSLAB) COPY_SLAB(s + 1, (s + 1) & 1);
        if (q + 3 < NQ) COPY_B(q + 3, (q + 3) & 3);
        CP_COMMIT();                         // exactly one group per iteration

        const uint32_t Aaddr = sbase + (s & 1) * SLAB_BYTES;
        const uint32_t Baddr = sbase + BRING_OFF + (q & 3) * BTILE_BYTES;
        const int voff = v * (2 * RSH);
#pragma unroll
        for (int ks = 0; ks < 4; ks++) {
            const int k0 = ks * 16;
            uint32_t Ar[2][4], Br[2][4];
            ldm4(Ar[0], Aaddr + 2 * (a_base[0] + voff + k0));
            ldm4(Ar[1], Aaddr + 2 * (a_base[1] + voff + k0));
            ldm4(Br[0], Baddr + 2 * (b_base[0] + k0));
            ldm4(Br[1], Baddr + 2 * (b_base[1] + k0));
#pragma unroll
            for (int mt = 0; mt < 2; mt++)
#pragma unroll
                for (int nt = 0; nt < 4; nt++)
                    mma_f16(acc[mt][nt], Ar[mt][0], Ar[mt][1], Ar[mt][2], Ar[mt][3],
                            Br[nt >> 1][(nt & 1) * 2], Br[nt >> 1][(nt & 1) * 2 + 1]);
        }
    }
    CP_WAIT(0);

    // ---------------- epilogue: logits -> smem -> softmax -> g_attn ----------
    __syncthreads();
    float* lg = (float*)smem;               // [128][66]
#pragma unroll
    for (int mt = 0; mt < 2; mt++) {
        const int row0 = mbase + mt * 16 + gid;
#pragma unroll
        for (int nt = 0; nt < 4; nt++) {
            const int col = nbase + nt * 8 + tg * 2;
            *(float2*)&lg[row0 * 66 + col] =
                make_float2(acc[mt][nt][0], acc[mt][nt][1]);
            *(float2*)&lg[(row0 + 8) * 66 + col] =
                make_float2(acc[mt][nt][2], acc[mt][nt][3]);
        }
    }
    __syncthreads();
    if (tid < 128) {
        const float* p = lg + tid * 66;
        float e[OC2];
        float mx = -1e30f;
#pragma unroll
        for (int k = 0; k < OC2; k++) {
            e[k] = p[k] + __ldg(&g_b12[k]);
            mx = fmaxf(mx, e[k]);
        }
        float s = 0.f;
#pragma unroll
        for (int k = 0; k < OC2; k++) { e[k] = __expf(e[k] - mx); s += e[k]; }
        const float inv = 1.f / s;
        const int h = hr0 + (tid >> 6), w = tid & 63;
        float* dst = g_attn + ((size_t)(b * OC2) * HH + h) * WW + w;
#pragma unroll
        for (int k = 0; k < OC2; k++)
            dst[(size_t)k * (HH * WW)] = e[k] * inv;
    }
#undef COPY_SLAB
#undef COPY_B
}

// ---------------------------------------------------------------------------
// Gather: out[b,c,h,w] = sum_k attn[b,k,h,w] * xpad[b,c,h+2u,w+2v]
// 2 channels per group, 3-buffer cp.async ring, 1 barrier per group.
// ---------------------------------------------------------------------------
__global__ __launch_bounds__(256) void gather_kernel(float* __restrict__ out) {
    const int tile = blockIdx.x;                 // 8 h-tiles x 4 w-tiles
    const int h0 = (tile >> 2) * 8, w0 = (tile & 3) * 16;
    const int b = blockIdx.z;
    const int tid = threadIdx.x;
    const int sub = tid >> 7, stid = tid & 127;
    const int rr = stid >> 4, cc = stid & 15;
    const int h = h0 + rr, w = w0 + cc;
    const int c0 = blockIdx.y * 128 + sub * 64;

    __shared__ __align__(16) float xsm[3][2][2][20 * GSTRIDE];

    float attn[OC2];
#pragma unroll
    for (int k = 0; k < OC2; k++)
        attn[k] = g_attn[(((size_t)(b * OC2 + k)) * HH + h) * WW + w];

    uint32_t sb[3][2];
#pragma unroll
    for (int s = 0; s < 3; s++)
#pragma unroll
        for (int ch = 0; ch < 2; ch++) sb[s][ch] = smem_u32(&xsm[s][sub][ch][0]);

    const float* plane0 = g_xpad + (((size_t)(b * CIN + c0)) * XP + h0) * XP + w0;

#define CPG(g, st) do {                                                         \
    for (int _ch = 0; _ch < 2; _ch++) {                                         \
        const float* _src = plane0 + (size_t)(2 * (g) + _ch) * XP * XP;         \
        const uint32_t _d = sb[st][_ch];                                        \
        for (int _i = stid; _i < 140; _i += 128) {                              \
            int _r = _i / 7, _j = _i - _r * 7;                                  \
            cp16(_d + (_r * GSTRIDE + _j * 4) * 4, _src + _r * XP + _j * 4);    \
        }                                                                       \
    }                                                                           \
} while (0)

    CPG(0, 0); CP_COMMIT();
    CPG(1, 1); CP_COMMIT();

#pragma unroll 1
    for (int g = 0; g < 32; g++) {
        CP_WAIT(1);
        __syncthreads();
        if (g + 2 < 32) { CPG(g + 2, (g + 2) % 3); }
        CP_COMMIT();

        const float* xs0 = &xsm[g % 3][sub][0][0];
        const float* xs1 = &xsm[g % 3][sub][1][0];
        float o0 = 0.f, o1 = 0.f;
#pragma unroll
        for (int u = 0; u < 7; u++)
#pragma unroll
            for (int v = 0; v < 7; v++) {
                const int idx = (rr + 2 * u) * GSTRIDE + cc + 2 * v;
                const float a = attn[u * 7 + v];
                o0 = fmaf(a, xs0[idx], o0);
                o1 = fmaf(a, xs1[idx], o1);
            }
        float* dst = out + (((size_t)(b * CIN + c0 + 2 * g)) * HH + h) * WW + w;
        dst[0] = o0;
        dst[HH * WW] = o1;
    }
#undef CPG
}

// ---------------------------------------------------------------------------
extern "C" void kernel_launch(void* const* d_in, const int* in_sizes, int n_in,
                              void* d_out, int out_size)
{
    const float* x  = (const float*)d_in[0];
    const float* w1 = (const float*)d_in[1];
    const float* b1 = (const float*)d_in[2];
    const float* w2 = (const float*)d_in[3];
    const float* b2 = (const float*)d_in[4];
    float* out = (float*)d_out;

    cudaFuncSetAttribute(conv_mma, cudaFuncAttributeMaxDynamicSharedMemorySize,
                         SMEM_CONV);

    pad_x<<<dim3(CIN, 4), 256>>>(x);
    nhwc_pad<<<dim3(HH, 4), 256>>>(x);
    fuse_w<<<49, 256>>>(w1, w2);
    bias_fuse<<<49, 128>>>(w2, b1, b2);
    conv_mma<<<dim3(32, 4), 256, SMEM_CONV>>>();
    gather_kernel<<<dim3(32, 2, 4), 256>>>(out);
}

// round 8
// speedup vs baseline: 11.1666x; 1.3312x over previous
#include <cuda_runtime.h>
#include <cuda_fp16.h>
#include <cstdint>

#define HH 64
#define WW 64
#define CIN 256
#define XP 76
#define OC2 49
#define KTOT 12544              // 49 taps * 256 ic
#define NQ 98                   // K chunks of 128 (14 slabs x 7 v)
#define NSLAB 14
#define RSH 136                 // smem row stride (halves): 68 words % 32 == 4 -> conflict-free
#define SLAB_BYTES (152 * RSH * 2)        // 41344
#define BTILE_BYTES (64 * RSH * 2)        // 17408
#define BRING_OFF (2 * SLAB_BYTES)        // 82688
#define SMEM_CONV (2 * SLAB_BYTES + 4 * BTILE_BYTES)   // 152320
#define GSTRIDE 48
#define SMEM_FW (25088 + 128 * 130 * 4)   // w2s + w1 tile = 91648

// Scratch (device globals: zero-initialized, allocation-free, graph-capturable)
__device__ float  g_xpad[4 * CIN * XP * XP];     // NCHW padded fp32 (gather); borders stay 0
__device__ __half g_xn[4 * XP * XP * CIN];       // NHWC padded fp16 (conv A); borders stay 0
__device__ __half g_w12t[64 * KTOT];             // fused W^T [oc64][tap*256+ic] fp16; oc>=49 stay 0
__device__ float  g_b12[OC2];                    // fused bias (fp32)
__device__ float  g_attn[4 * OC2 * HH * WW];     // softmax attention

// ---------------- helpers ----------------
__device__ __forceinline__ uint32_t smem_u32(const void* p) {
    uint32_t a;
    asm("{ .reg .u64 t; cvta.to.shared.u64 t, %1; cvt.u32.u64 %0, t; }" : "=r"(a) : "l"(p));
    return a;
}
__device__ __forceinline__ void cp16(uint32_t d, const void* s) {
    asm volatile("cp.async.cg.shared.global [%0], [%1], 16;" :: "r"(d), "l"(s));
}
#define CP_COMMIT() asm volatile("cp.async.commit_group;")
#define CP_WAIT(n)  asm volatile("cp.async.wait_group %0;" :: "n"(n))

__device__ __forceinline__ void mma_f16(float* c, uint32_t a0, uint32_t a1,
                                        uint32_t a2, uint32_t a3,
                                        uint32_t b0, uint32_t b1) {
    asm volatile(
        "mma.sync.aligned.m16n8k16.row.col.f32.f16.f16.f32 "
        "{%0,%1,%2,%3},{%4,%5,%6,%7},{%8,%9},{%0,%1,%2,%3};"
        : "+f"(c[0]), "+f"(c[1]), "+f"(c[2]), "+f"(c[3])
        : "r"(a0), "r"(a1), "r"(a2), "r"(a3), "r"(b0), "r"(b1));
}
__device__ __forceinline__ void ldm4(uint32_t* r, uint32_t addr) {
    asm volatile("ldmatrix.sync.aligned.m8n8.x4.shared.b16 {%0,%1,%2,%3}, [%4];"
        : "=r"(r[0]), "=r"(r[1]), "=r"(r[2]), "=r"(r[3]) : "r"(addr));
}

// ---------------------------------------------------------------------------
// Combined prep: x -> g_xpad (NCHW fp32, interior) and g_xn (NHWC fp16, interior)
// grid (64 rows, 4 b)
// ---------------------------------------------------------------------------
__global__ __launch_bounds__(256) void prep_x(const float* __restrict__ x) {
    const int h = blockIdx.x, b = blockIdx.y;
    __half* outr = g_xn + (((size_t)b * XP + (h + 6))) * XP * CIN;
    __shared__ float sm[128 * 65];
    for (int half_i = 0; half_i < 2; half_i++) {
        const int ich = half_i * 128;
        for (int idx = threadIdx.x; idx < 128 * 64; idx += 256) {
            int icl = idx >> 6, w = idx & 63;
            sm[icl * 65 + w] = x[(((size_t)(b * CIN + ich + icl)) * HH + h) * WW + w];
        }
        __syncthreads();
        // NHWC fp16 (transposed)
        for (int idx = threadIdx.x; idx < 64 * 128; idx += 256) {
            int w = idx >> 7, icl = idx & 127;
            outr[(size_t)(w + 6) * CIN + ich + icl] = __float2half_rn(sm[icl * 65 + w]);
        }
        // NCHW fp32 padded rows
        for (int idx = threadIdx.x; idx < 128 * 64; idx += 256) {
            int icl = idx >> 6, w = idx & 63;
            g_xpad[((size_t)(b * CIN + ich + icl)) * XP * XP + (h + 6) * XP + w + 6] =
                sm[icl * 65 + w];
        }
        __syncthreads();
    }
}

// ---------------------------------------------------------------------------
// Fused weights as tiled GEMM over w1's native k' = ic*49+tap ordering.
// Block: one 128-wide k' tile (98 blocks). Coalesced w1 loads; scatter store
// remapped to k = tap*256+ic.
// ---------------------------------------------------------------------------
__global__ __launch_bounds__(256) void fuse_w(const float* __restrict__ w1,
                                              const float* __restrict__ w2) {
    extern __shared__ float fsm[];
    float* w2s = fsm;                 // [49*128]
    float* sm  = fsm + OC2 * 128;     // [128][130]
    const int tid = threadIdx.x;
    const int k0 = blockIdx.x * 128;

    for (int i = tid; i < OC2 * 128; i += 256) w2s[i] = w2[i];
    for (int i = tid; i < 128 * 128; i += 256) {
        int m = i >> 7, kcl = i & 127;
        sm[m * 130 + kcl] = w1[(size_t)m * KTOT + k0 + kcl];
    }
    __syncthreads();

    const int och = tid >> 6;                 // 0..3, uniform per warp
    const int kc0 = (tid & 63) * 2;
    const int oc0 = och * 12;
    const int ocn = (och < 3) ? 12 : 13;

    float accx[13], accy[13];
#pragma unroll
    for (int j = 0; j < 13; j++) { accx[j] = 0.f; accy[j] = 0.f; }

#pragma unroll 4
    for (int m = 0; m < 128; m++) {
        const float2 a = *(const float2*)&sm[m * 130 + kc0];
#pragma unroll
        for (int j = 0; j < 13; j++) {
            if (j < ocn) {
                const float wv = w2s[(oc0 + j) * 128 + m];
                accx[j] = fmaf(wv, a.x, accx[j]);
                accy[j] = fmaf(wv, a.y, accy[j]);
            }
        }
    }

#pragma unroll
    for (int j = 0; j < 13; j++) {
        if (j < ocn) {
#pragma unroll
            for (int e = 0; e < 2; e++) {
                const int kp = k0 + kc0 + e;
                const int ic = kp / 49, tap = kp - ic * 49;
                g_w12t[(size_t)(oc0 + j) * KTOT + tap * 256 + ic] =
                    __float2half_rn(e ? accy[j] : accx[j]);
            }
        }
    }
}

__global__ __launch_bounds__(128) void bias_fuse(const float* __restrict__ w2,
                                                 const float* __restrict__ b1,
                                                 const float* __restrict__ b2) {
    const int oc = blockIdx.x, tid = threadIdx.x;
    float v = w2[oc * 128 + tid] * b1[tid];
#pragma unroll
    for (int off = 16; off > 0; off >>= 1)
        v += __shfl_xor_sync(0xFFFFFFFFu, v, off);
    __shared__ float ws[4];
    if ((tid & 31) == 0) ws[tid >> 5] = v;
    __syncthreads();
    if (tid == 0) g_b12[oc] = ws[0] + ws[1] + ws[2] + ws[3] + b2[oc];
}

// ---------------------------------------------------------------------------
// fp16 mma.sync implicit-GEMM conv + fused bias + softmax.
// CTA: M=128 px (2 rows x 64 cols), N=64 oc. 14 slabs x 7 v-chunks, K=128 each.
// ldmatrix.x4; copies before MMA; one barrier per K=128 chunk.
// ---------------------------------------------------------------------------
__global__ __launch_bounds__(256) void conv_mma() {
    extern __shared__ __align__(16) char smem[];
    const uint32_t sbase = smem_u32(smem);
    const int tid = threadIdx.x, wid = tid >> 5, lane = tid & 31;
    const int gid = lane >> 2, tg = lane & 3;
    const int hr0 = blockIdx.x * 2, b = blockIdx.y;
    const int mbase = (wid >> 1) * 32, nbase = (wid & 1) * 32;

    float acc[2][4][4];
#pragma unroll
    for (int mt = 0; mt < 2; mt++)
#pragma unroll
        for (int nt = 0; nt < 4; nt++)
#pragma unroll
            for (int r = 0; r < 4; r++) acc[mt][nt][r] = 0.f;

    // ldmatrix per-lane base offsets (in halves)
    int a_base[2], b_base[2];
    {
        const int l = lane;
        const int rsel = ((l >> 3) & 1) * 8 + (l & 7);
#pragma unroll
        for (int mt = 0; mt < 2; mt++)
            a_base[mt] = ((mbase >> 6) * 76 + (mbase & 63) + mt * 16 + rsel) * RSH
                         + (l >> 4) * 8;
#pragma unroll
        for (int ntp = 0; ntp < 2; ntp++)
            b_base[ntp] = (nbase + ntp * 16 + (l >> 4) * 8 + (l & 7)) * RSH
                          + ((l >> 3) & 1) * 8;
    }

    const __half* xb = g_xn + (size_t)b * XP * XP * CIN;

// slab s = u*2+icb : 2 padded rows (hr0+2u, +1) x 76 cols x 128 ic
#define COPY_SLAB(s, slot) do {                                                 \
    const int _u = (s) >> 1, _icb = (s) & 1;                                    \
    const __half* _src = xb + ((size_t)(hr0 + 2 * _u) * XP) * CIN + _icb * 128; \
    const uint32_t _dst = sbase + (slot) * SLAB_BYTES;                          \
    for (int _i = tid; _i < 2432; _i += 256) {                                  \
        int _row = _i >> 4, _j = _i & 15;                                       \
        int _pr = _row / 76, _col = _row - _pr * 76;                            \
        cp16(_dst + _row * (RSH * 2) + _j * 16,                                 \
             _src + ((size_t)_pr * XP + _col) * CIN + _j * 8);                  \
    }                                                                           \
} while (0)

#define COPY_B(q, slot) do {                                                    \
    const int _s = (q) / 7, _v = (q) - _s * 7;                                  \
    const int _tap = (_s >> 1) * 7 + _v, _icb = _s & 1;                         \
    const __half* _bs = g_w12t + _tap * 256 + _icb * 128;                       \
    const uint32_t _dst = sbase + BRING_OFF + (slot) * BTILE_BYTES;             \
    for (int _i = tid; _i < 1024; _i += 256) {                                  \
        int _oc = _i >> 4, _j = _i & 15;                                        \
        cp16(_dst + _oc * (RSH * 2) + _j * 16, _bs + (size_t)_oc * KTOT + _j * 8); \
    }                                                                           \
} while (0)

    COPY_SLAB(0, 0); COPY_B(0, 0); CP_COMMIT();
    COPY_SLAB(1, 1); COPY_B(1, 1); CP_COMMIT();
    COPY_B(2, 2); CP_COMMIT();

#pragma unroll 1
    for (int q = 0; q < NQ; q++) {
        CP_WAIT(2);
        __syncthreads();
        const int s = q / 7, v = q - s * 7;
        // prefetch first: targets are buffers whose readers passed the sync above
        if (v == 0 && s >= 1 && s + 1 < NSLAB) COPY_SLAB(s + 1, (s + 1) & 1);
        if (q + 3 < NQ) COPY_B(q + 3, (q + 3) & 3);
        CP_COMMIT();                         // exactly one group per iteration

        const uint32_t Aaddr = sbase + (s & 1) * SLAB_BYTES;
        const uint32_t Baddr = sbase + BRING_OFF + (q & 3) * BTILE_BYTES;
        const int voff = v * (2 * RSH);
#pragma unroll
        for (int ks = 0; ks < 8; ks++) {
            const int k0 = ks * 16;
            uint32_t Ar[2][4], Br[2][4];
            ldm4(Ar[0], Aaddr + 2 * (a_base[0] + voff + k0));
            ldm4(Ar[1], Aaddr + 2 * (a_base[1] + voff + k0));
            ldm4(Br[0], Baddr + 2 * (b_base[0] + k0));
            ldm4(Br[1], Baddr + 2 * (b_base[1] + k0));
#pragma unroll
            for (int mt = 0; mt < 2; mt++)
#pragma unroll
                for (int nt = 0; nt < 4; nt++)
                    mma_f16(acc[mt][nt], Ar[mt][0], Ar[mt][1], Ar[mt][2], Ar[mt][3],
                            Br[nt >> 1][(nt & 1) * 2], Br[nt >> 1][(nt & 1) * 2 + 1]);
        }
    }
    CP_WAIT(0);

    // ---------------- epilogue: logits -> smem -> softmax -> g_attn ----------
    __syncthreads();
    float* lg = (float*)smem;               // [128][66]
#pragma unroll
    for (int mt = 0; mt < 2; mt++) {
        const int row0 = mbase + mt * 16 + gid;
#pragma unroll
        for (int nt = 0; nt < 4; nt++) {
            const int col = nbase + nt * 8 + tg * 2;
            *(float2*)&lg[row0 * 66 + col] =
                make_float2(acc[mt][nt][0], acc[mt][nt][1]);
            *(float2*)&lg[(row0 + 8) * 66 + col] =
                make_float2(acc[mt][nt][2], acc[mt][nt][3]);
        }
    }
    __syncthreads();
    if (tid < 128) {
        const float* p = lg + tid * 66;
        float e[OC2];
        float mx = -1e30f;
#pragma unroll
        for (int k = 0; k < OC2; k++) {
            e[k] = p[k] + __ldg(&g_b12[k]);
            mx = fmaxf(mx, e[k]);
        }
        float s = 0.f;
#pragma unroll
        for (int k = 0; k < OC2; k++) { e[k] = __expf(e[k] - mx); s += e[k]; }
        const float inv = 1.f / s;
        const int h = hr0 + (tid >> 6), w = tid & 63;
        float* dst = g_attn + ((size_t)(b * OC2) * HH + h) * WW + w;
#pragma unroll
        for (int k = 0; k < OC2; k++)
            dst[(size_t)k * (HH * WW)] = e[k] * inv;
    }
#undef COPY_SLAB
#undef COPY_B
}

// ---------------------------------------------------------------------------
// Gather: out[b,c,h,w] = sum_k attn[b,k,h,w] * xpad[b,c,h+2u,w+2v]
// 2 channels per group, 3-buffer cp.async ring, 1 barrier per group.
// ---------------------------------------------------------------------------
__global__ __launch_bounds__(256) void gather_kernel(float* __restrict__ out) {
    const int tile = blockIdx.x;                 // 8 h-tiles x 4 w-tiles
    const int h0 = (tile >> 2) * 8, w0 = (tile & 3) * 16;
    const int b = blockIdx.z;
    const int tid = threadIdx.x;
    const int sub = tid >> 7, stid = tid & 127;
    const int rr = stid >> 4, cc = stid & 15;
    const int h = h0 + rr, w = w0 + cc;
    const int c0 = blockIdx.y * 128 + sub * 64;

    __shared__ __align__(16) float xsm[3][2][2][20 * GSTRIDE];

    float attn[OC2];
#pragma unroll
    for (int k = 0; k < OC2; k++)
        attn[k] = g_attn[(((size_t)(b * OC2 + k)) * HH + h) * WW + w];

    uint32_t sb[3][2];
#pragma unroll
    for (int s = 0; s < 3; s++)
#pragma unroll
        for (int ch = 0; ch < 2; ch++) sb[s][ch] = smem_u32(&xsm[s][sub][ch][0]);

    const float* plane0 = g_xpad + (((size_t)(b * CIN + c0)) * XP + h0) * XP + w0;

#define CPG(g, st) do {                                                         \
    for (int _ch = 0; _ch < 2; _ch++) {                                         \
        const float* _src = plane0 + (size_t)(2 * (g) + _ch) * XP * XP;         \
        const uint32_t _d = sb[st][_ch];                                        \
        for (int _i = stid; _i < 140; _i += 128) {                              \
            int _r = _i / 7, _j = _i - _r * 7;                                  \
            cp16(_d + (_r * GSTRIDE + _j * 4) * 4, _src + _r * XP + _j * 4);    \
        }                                                                       \
    }                                                                           \
} while (0)

    CPG(0, 0); CP_COMMIT();
    CPG(1, 1); CP_COMMIT();

#pragma unroll 1
    for (int g = 0; g < 32; g++) {
        CP_WAIT(1);
        __syncthreads();
        if (g + 2 < 32) { CPG(g + 2, (g + 2) % 3); }
        CP_COMMIT();

        const float* xs0 = &xsm[g % 3][sub][0][0];
        const float* xs1 = &xsm[g % 3][sub][1][0];
        float o0 = 0.f, o1 = 0.f;
#pragma unroll
        for (int u = 0; u < 7; u++)
#pragma unroll
            for (int v = 0; v < 7; v++) {
                const int idx = (rr + 2 * u) * GSTRIDE + cc + 2 * v;
                const float a = attn[u * 7 + v];
                o0 = fmaf(a, xs0[idx], o0);
                o1 = fmaf(a, xs1[idx], o1);
            }
        float* dst = out + (((size_t)(b * CIN + c0 + 2 * g)) * HH + h) * WW + w;
        dst[0] = o0;
        dst[HH * WW] = o1;
    }
#undef CPG
}

// ---------------------------------------------------------------------------
extern "C" void kernel_launch(void* const* d_in, const int* in_sizes, int n_in,
                              void* d_out, int out_size)
{
    const float* x  = (const float*)d_in[0];
    const float* w1 = (const float*)d_in[1];
    const float* b1 = (const float*)d_in[2];
    const float* w2 = (const float*)d_in[3];
    const float* b2 = (const float*)d_in[4];
    float* out = (float*)d_out;

    cudaFuncSetAttribute(conv_mma, cudaFuncAttributeMaxDynamicSharedMemorySize,
                         SMEM_CONV);
    cudaFuncSetAttribute(fuse_w, cudaFuncAttributeMaxDynamicSharedMemorySize,
                         SMEM_FW);

    prep_x<<<dim3(HH, 4), 256>>>(x);
    fuse_w<<<98, 256, SMEM_FW>>>(w1, w2);
    bias_fuse<<<49, 128>>>(w2, b1, b2);
    conv_mma<<<dim3(32, 4), 256, SMEM_CONV>>>();
    gather_kernel<<<dim3(32, 2, 4), 256>>>(out);
}

// round 9
// speedup vs baseline: 11.6673x; 1.0448x over previous
#include <cuda_runtime.h>
#include <cuda_fp16.h>
#include <cstdint>

#define HH 64
#define WW 64
#define CIN 256
#define XP 76
#define OC2 49
#define KTOT 12544              // 49 taps * 256 ic
#define NQ 49                   // chunks per CTA: 1 tap x 128 ic (this CTA's half)
#define SLAB_BYTES (152 * 256)  // 2 padded rows x 76 cols x 128 ic fp16, swizzled
#define BTILE_BYTES (64 * 256)  // 64 oc x 128 ic fp16, swizzled
#define BRING_OFF (2 * SLAB_BYTES)
#define SMEM_CONV (BRING_OFF + 2 * BTILE_BYTES)   // 110592 -> 2 CTAs/SM
#define GSTRIDE 48
#define SMEM_FW (25088 + 128 * 130 * 4)

// Scratch (device globals: zero-initialized, allocation-free, graph-capturable)
__device__ float  g_xpad[4 * CIN * XP * XP];     // NCHW padded fp32 (gather)
__device__ __half g_xn[4 * XP * XP * CIN];       // NHWC padded fp16 (conv A)
__device__ __half g_w12t[64 * KTOT];             // fused W^T [oc64][tap*256+ic] fp16
__device__ float  g_b12[OC2];                    // fused bias
__device__ float  g_k2[2 * 4 * OC2 * HH * WW];   // partial logits [icq][b][oc][px]
__device__ float  g_attn[4 * OC2 * HH * WW];     // softmax attention

// ---------------- helpers ----------------
__device__ __forceinline__ uint32_t smem_u32(const void* p) {
    uint32_t a;
    asm("{ .reg .u64 t; cvta.to.shared.u64 t, %1; cvt.u32.u64 %0, t; }" : "=r"(a) : "l"(p));
    return a;
}
__device__ __forceinline__ void cp16(uint32_t d, const void* s) {
    asm volatile("cp.async.cg.shared.global [%0], [%1], 16;" :: "r"(d), "l"(s));
}
#define CP_COMMIT() asm volatile("cp.async.commit_group;")
#define CP_WAIT(n)  asm volatile("cp.async.wait_group %0;" :: "n"(n))

__device__ __forceinline__ void mma_f16(float* c, uint32_t a0, uint32_t a1,
                                        uint32_t a2, uint32_t a3,
                                        uint32_t b0, uint32_t b1) {
    asm volatile(
        "mma.sync.aligned.m16n8k16.row.col.f32.f16.f16.f32 "
        "{%0,%1,%2,%3},{%4,%5,%6,%7},{%8,%9},{%0,%1,%2,%3};"
        : "+f"(c[0]), "+f"(c[1]), "+f"(c[2]), "+f"(c[3])
        : "r"(a0), "r"(a1), "r"(a2), "r"(a3), "r"(b0), "r"(b1));
}
__device__ __forceinline__ void ldm4(uint32_t* r, uint32_t addr) {
    asm volatile("ldmatrix.sync.aligned.m8n8.x4.shared.b16 {%0,%1,%2,%3}, [%4];"
        : "=r"(r[0]), "=r"(r[1]), "=r"(r[2]), "=r"(r[3]) : "r"(addr));
}

// ---------------------------------------------------------------------------
// Combined prep: x -> g_xpad (NCHW fp32) and g_xn (NHWC fp16), interiors only
// ---------------------------------------------------------------------------
__global__ __launch_bounds__(256) void prep_x(const float* __restrict__ x) {
    const int h = blockIdx.x, b = blockIdx.y;
    __half* outr = g_xn + (((size_t)b * XP + (h + 6))) * XP * CIN;
    __shared__ float sm[128 * 65];
    for (int half_i = 0; half_i < 2; half_i++) {
        const int ich = half_i * 128;
        for (int idx = threadIdx.x; idx < 128 * 64; idx += 256) {
            int icl = idx >> 6, w = idx & 63;
            sm[icl * 65 + w] = x[(((size_t)(b * CIN + ich + icl)) * HH + h) * WW + w];
        }
        __syncthreads();
        for (int idx = threadIdx.x; idx < 64 * 128; idx += 256) {
            int w = idx >> 7, icl = idx & 127;
            outr[(size_t)(w + 6) * CIN + ich + icl] = __float2half_rn(sm[icl * 65 + w]);
        }
        for (int idx = threadIdx.x; idx < 128 * 64; idx += 256) {
            int icl = idx >> 6, w = idx & 63;
            g_xpad[((size_t)(b * CIN + ich + icl)) * XP * XP + (h + 6) * XP + w + 6] =
                sm[icl * 65 + w];
        }
        __syncthreads();
    }
}

// ---------------------------------------------------------------------------
// Fused weights as tiled GEMM over w1's native k' = ic*49+tap ordering.
// ---------------------------------------------------------------------------
__global__ __launch_bounds__(256) void fuse_w(const float* __restrict__ w1,
                                              const float* __restrict__ w2) {
    extern __shared__ float fsm[];
    float* w2s = fsm;
    float* sm  = fsm + OC2 * 128;
    const int tid = threadIdx.x;
    const int k0 = blockIdx.x * 128;

    for (int i = tid; i < OC2 * 128; i += 256) w2s[i] = w2[i];
    for (int i = tid; i < 128 * 128; i += 256) {
        int m = i >> 7, kcl = i & 127;
        sm[m * 130 + kcl] = w1[(size_t)m * KTOT + k0 + kcl];
    }
    __syncthreads();

    const int och = tid >> 6;
    const int kc0 = (tid & 63) * 2;
    const int oc0 = och * 12;
    const int ocn = (och < 3) ? 12 : 13;

    float accx[13], accy[13];
#pragma unroll
    for (int j = 0; j < 13; j++) { accx[j] = 0.f; accy[j] = 0.f; }

#pragma unroll 4
    for (int m = 0; m < 128; m++) {
        const float2 a = *(const float2*)&sm[m * 130 + kc0];
#pragma unroll
        for (int j = 0; j < 13; j++) {
            if (j < ocn) {
                const float wv = w2s[(oc0 + j) * 128 + m];
                accx[j] = fmaf(wv, a.x, accx[j]);
                accy[j] = fmaf(wv, a.y, accy[j]);
            }
        }
    }
#pragma unroll
    for (int j = 0; j < 13; j++) {
        if (j < ocn) {
#pragma unroll
            for (int e = 0; e < 2; e++) {
                const int kp = k0 + kc0 + e;
                const int ic = kp / 49, tap = kp - ic * 49;
                g_w12t[(size_t)(oc0 + j) * KTOT + tap * 256 + ic] =
                    __float2half_rn(e ? accy[j] : accx[j]);
            }
        }
    }
}

__global__ __launch_bounds__(128) void bias_fuse(const float* __restrict__ w2,
                                                 const float* __restrict__ b1,
                                                 const float* __restrict__ b2) {
    const int oc = blockIdx.x, tid = threadIdx.x;
    float v = w2[oc * 128 + tid] * b1[tid];
#pragma unroll
    for (int off = 16; off > 0; off >>= 1)
        v += __shfl_xor_sync(0xFFFFFFFFu, v, off);
    __shared__ float ws[4];
    if ((tid & 31) == 0) ws[tid >> 5] = v;
    __syncthreads();
    if (tid == 0) g_b12[oc] = ws[0] + ws[1] + ws[2] + ws[3] + b2[oc];
}

// ---------------------------------------------------------------------------
// fp16 mma.sync implicit-GEMM conv, K split across 2 CTAs (ic halves).
// CTA: M=128 px, N=64 oc, K=6272 in 49 chunks (1 tap x 128 ic).
// XOR-swizzled smem (256B rows), 2 CTAs/SM. Writes partial logits to g_k2.
// ---------------------------------------------------------------------------
__global__ __launch_bounds__(256) void conv_mma() {
    extern __shared__ __align__(16) char smem[];
    const uint32_t sbase = smem_u32(smem);
    const int tid = threadIdx.x, wid = tid >> 5, lane = tid & 31;
    const int gid = lane >> 2, tg = lane & 3;
    const int hr0 = blockIdx.x * 2, b = blockIdx.y, icq = blockIdx.z;
    const int mbase = (wid >> 1) * 32, nbase = (wid & 1) * 32;
    const int icbase = icq * 128;

    float acc[2][4][4];
#pragma unroll
    for (int mt = 0; mt < 2; mt++)
#pragma unroll
        for (int nt = 0; nt < 4; nt++)
#pragma unroll
            for (int r = 0; r < 4; r++) acc[mt][nt][r] = 0.f;

    // fragment row indices (pre-v); swizzle masks computed per chunk for A
    const int lhi16 = lane >> 4;            // 0/1 : A k-unit select
    const int bhi = (lane >> 3) & 1;        // 0/1 : B k-unit select
    int arow0[2];
    {
        const int rsel = ((lane >> 3) & 1) * 8 + (lane & 7);
#pragma unroll
        for (int mt = 0; mt < 2; mt++)
            arow0[mt] = (mbase >> 6) * 76 + (mbase & 63) + mt * 16 + rsel;
    }
    int brow[2];
#pragma unroll
    for (int ntp = 0; ntp < 2; ntp++)
        brow[ntp] = nbase + ntp * 16 + (lane >> 4) * 8 + (lane & 7);

    const __half* xb = g_xn + (size_t)b * XP * XP * CIN;

// slab u: 2 padded rows (hr0+2u, +1) x 76 cols x this CTA's 128 ic
#define COPY_SLAB(u, slot) do {                                                 \
    const __half* _src = xb + ((size_t)(hr0 + 2 * (u)) * XP) * CIN + icbase;    \
    const uint32_t _dst = sbase + (slot) * SLAB_BYTES;                          \
    for (int _i = tid; _i < 2432; _i += 256) {                                  \
        int _row = _i >> 4, _j = _i & 15;                                       \
        int _pr = _row / 76, _col = _row - _pr * 76;                            \
        cp16(_dst + _row * 256 + ((_j ^ (_row & 7)) << 4),                      \
             _src + ((size_t)_pr * XP + _col) * CIN + _j * 8);                  \
    }                                                                           \
} while (0)

// chunk q == tap q
#define COPY_B(q, slot) do {                                                    \
    const __half* _bs = g_w12t + (q) * 256 + icbase;                            \
    const uint32_t _dst = sbase + BRING_OFF + (slot) * BTILE_BYTES;             \
    for (int _i = tid; _i < 1024; _i += 256) {                                  \
        int _oc = _i >> 4, _j = _i & 15;                                        \
        cp16(_dst + _oc * 256 + ((_j ^ (_oc & 7)) << 4),                        \
             _bs + (size_t)_oc * KTOT + _j * 8);                                \
    }                                                                           \
} while (0)

    COPY_SLAB(0, 0); COPY_B(0, 0); CP_COMMIT();

#pragma unroll 1
    for (int q = 0; q < NQ; q++) {
        CP_WAIT(0);
        __syncthreads();
        const int s = q / 7, v = q - s * 7;
        if (v == 0 && s + 1 < 7) COPY_SLAB(s + 1, (s + 1) & 1);
        if (q + 1 < NQ) COPY_B(q + 1, (q + 1) & 1);
        CP_COMMIT();

        const uint32_t Aaddr = sbase + (s & 1) * SLAB_BYTES;
        const uint32_t Baddr = sbase + BRING_OFF + (q & 1) * BTILE_BYTES;
        uint32_t Abase[2], Bbase[2];
        int amask[2], bmask[2];
#pragma unroll
        for (int mt = 0; mt < 2; mt++) {
            const int r = arow0[mt] + 2 * v;
            Abase[mt] = Aaddr + r * 256;
            amask[mt] = r & 7;
        }
#pragma unroll
        for (int ntp = 0; ntp < 2; ntp++) {
            Bbase[ntp] = Baddr + brow[ntp] * 256;
            bmask[ntp] = brow[ntp] & 7;
        }
#pragma unroll
        for (int ks = 0; ks < 8; ks++) {
            uint32_t Ar[2][4], Br[2][4];
            ldm4(Ar[0], Abase[0] + (((2 * ks + lhi16) ^ amask[0]) << 4));
            ldm4(Ar[1], Abase[1] + (((2 * ks + lhi16) ^ amask[1]) << 4));
            ldm4(Br[0], Bbase[0] + (((2 * ks + bhi) ^ bmask[0]) << 4));
            ldm4(Br[1], Bbase[1] + (((2 * ks + bhi) ^ bmask[1]) << 4));
#pragma unroll
            for (int mt = 0; mt < 2; mt++)
#pragma unroll
                for (int nt = 0; nt < 4; nt++)
                    mma_f16(acc[mt][nt], Ar[mt][0], Ar[mt][1], Ar[mt][2], Ar[mt][3],
                            Br[nt >> 1][(nt & 1) * 2], Br[nt >> 1][(nt & 1) * 2 + 1]);
        }
    }

    // ---------------- epilogue: partial logits -> g_k2 (coalesced) ----------
    __syncthreads();
    float* lg = (float*)smem;               // [128][66]
#pragma unroll
    for (int mt = 0; mt < 2; mt++) {
        const int row0 = mbase + mt * 16 + gid;
#pragma unroll
        for (int nt = 0; nt < 4; nt++) {
            const int col = nbase + nt * 8 + tg * 2;
            *(float2*)&lg[row0 * 66 + col] =
                make_float2(acc[mt][nt][0], acc[mt][nt][1]);
            *(float2*)&lg[(row0 + 8) * 66 + col] =
                make_float2(acc[mt][nt][2], acc[mt][nt][3]);
        }
    }
    __syncthreads();
    if (tid < 128) {
        const float* p = lg + tid * 66;
        float* dst = g_k2 + ((size_t)(icq * 4 + b) * OC2) * (HH * WW)
                     + (hr0 + (tid >> 6)) * WW + (tid & 63);
#pragma unroll
        for (int k = 0; k < OC2; k++)
            dst[(size_t)k * (HH * WW)] = p[k];
    }
#undef COPY_SLAB
#undef COPY_B
}

// ---------------------------------------------------------------------------
// Sum 2 ic-partials + fused bias, softmax over 49 channels -> g_attn
// ---------------------------------------------------------------------------
__global__ __launch_bounds__(128) void softmax_k() {
    const int b = blockIdx.y;
    const int px = blockIdx.x * 128 + threadIdx.x;
    __shared__ float bs[OC2];
    if (threadIdx.x < OC2) bs[threadIdx.x] = g_b12[threadIdx.x];
    __syncthreads();

    const float* p0 = g_k2 + ((size_t)(0 * 4 + b) * OC2) * (HH * WW) + px;
    const float* p1 = g_k2 + ((size_t)(1 * 4 + b) * OC2) * (HH * WW) + px;
    float v[OC2];
    float mx = -1e30f;
#pragma unroll
    for (int k = 0; k < OC2; k++) {
        v[k] = bs[k] + p0[(size_t)k * (HH * WW)] + p1[(size_t)k * (HH * WW)];
        mx = fmaxf(mx, v[k]);
    }
    float s = 0.f;
#pragma unroll
    for (int k = 0; k < OC2; k++) { v[k] = __expf(v[k] - mx); s += v[k]; }
    const float inv = 1.f / s;
#pragma unroll
    for (int k = 0; k < OC2; k++)
        g_attn[((size_t)(b * OC2 + k)) * (HH * WW) + px] = v[k] * inv;
}

// ---------------------------------------------------------------------------
// Gather: out[b,c,h,w] = sum_k attn[b,k,h,w] * xpad[b,c,h+2u,w+2v]
// 4 channels per group, 3-buffer cp.async ring, 1 barrier per group.
// ---------------------------------------------------------------------------
__global__ __launch_bounds__(256) void gather_kernel(float* __restrict__ out) {
    const int tile = blockIdx.x;                 // 8 h-tiles x 4 w-tiles
    const int h0 = (tile >> 2) * 8, w0 = (tile & 3) * 16;
    const int b = blockIdx.z;
    const int tid = threadIdx.x;
    const int sub = tid >> 7, stid = tid & 127;
    const int rr = stid >> 4, cc = stid & 15;
    const int h = h0 + rr, w = w0 + cc;
    const int c0 = blockIdx.y * 128 + sub * 64;

    __shared__ __align__(16) float xsm[3][2][4][20 * GSTRIDE];

    float attn[OC2];
#pragma unroll
    for (int k = 0; k < OC2; k++)
        attn[k] = g_attn[(((size_t)(b * OC2 + k)) * HH + h) * WW + w];

    uint32_t sb[3];
#pragma unroll
    for (int s = 0; s < 3; s++) sb[s] = smem_u32(&xsm[s][sub][0][0]);

    const float* plane0 = g_xpad + (((size_t)(b * CIN + c0)) * XP + h0) * XP + w0;

#define CPG(g, st) do {                                                         \
    for (int _ch = 0; _ch < 4; _ch++) {                                         \
        const float* _src = plane0 + (size_t)(4 * (g) + _ch) * XP * XP;         \
        const uint32_t _d = sb[st] + _ch * (20 * GSTRIDE * 4);                  \
        for (int _i = stid; _i < 140; _i += 128) {                              \
            int _r = _i / 7, _j = _i - _r * 7;                                  \
            cp16(_d + (_r * GSTRIDE + _j * 4) * 4, _src + _r * XP + _j * 4);    \
        }                                                                       \
    }                                                                           \
} while (0)

    CPG(0, 0); CP_COMMIT();
    CPG(1, 1); CP_COMMIT();

#pragma unroll 1
    for (int g = 0; g < 16; g++) {
        CP_WAIT(1);
        __syncthreads();
        if (g + 2 < 16) { CPG(g + 2, (g + 2) % 3); }
        CP_COMMIT();

        const float* xs = &xsm[g % 3][sub][0][0];
        float o0 = 0.f, o1 = 0.f, o2 = 0.f, o3 = 0.f;
#pragma unroll
        for (int u = 0; u < 7; u++)
#pragma unroll
            for (int v = 0; v < 7; v++) {
                const int idx = (rr + 2 * u) * GSTRIDE + cc + 2 * v;
                const float a = attn[u * 7 + v];
                o0 = fmaf(a, xs[idx], o0);
                o1 = fmaf(a, xs[idx + 960], o1);
                o2 = fmaf(a, xs[idx + 1920], o2);
                o3 = fmaf(a, xs[idx + 2880], o3);
            }
        float* dst = out + (((size_t)(b * CIN + c0 + 4 * g)) * HH + h) * WW + w;
        dst[0] = o0;
        dst[HH * WW] = o1;
        dst[2 * HH * WW] = o2;
        dst[3 * HH * WW] = o3;
    }
#undef CPG
}

// ---------------------------------------------------------------------------
extern "C" void kernel_launch(void* const* d_in, const int* in_sizes, int n_in,
                              void* d_out, int out_size)
{
    const float* x  = (const float*)d_in[0];
    const float* w1 = (const float*)d_in[1];
    const float* b1 = (const float*)d_in[2];
    const float* w2 = (const float*)d_in[3];
    const float* b2 = (const float*)d_in[4];
    float* out = (float*)d_out;

    cudaFuncSetAttribute(conv_mma, cudaFuncAttributeMaxDynamicSharedMemorySize,
                         SMEM_CONV);
    cudaFuncSetAttribute(fuse_w, cudaFuncAttributeMaxDynamicSharedMemorySize,
                         SMEM_FW);

    prep_x<<<dim3(HH, 4), 256>>>(x);
    fuse_w<<<98, 256, SMEM_FW>>>(w1, w2);
    bias_fuse<<<49, 128>>>(w2, b1, b2);
    conv_mma<<<dim3(32, 4, 2), 256, SMEM_CONV>>>();
    softmax_k<<<dim3(32, 4), 128>>>();
    gather_kernel<<<dim3(32, 2, 4), 256>>>(out);
}